// round 2
// baseline (speedup 1.0000x reference)
#include <cuda_runtime.h>
#include <stdint.h>

#define D 128
#define NMAX 100000
#define EMAX 1600000
#define NGRAPH 512
#define LN_EPS 1e-5f

// ---------------- scratch (no allocs allowed) ----------------
__device__ float d_bufG[(size_t)NMAX * D];   // g = (in @ W) * dinv[row]
__device__ float d_bufA[(size_t)NMAX * D];
__device__ float d_bufB[(size_t)NMAX * D];
__device__ float d_deg[NMAX];
__device__ float d_dinv[NMAX];
__device__ int   d_src[EMAX];
__device__ int   d_dst[EMAX];
__device__ int   d_batch32[NMAX];
__device__ float d_pooled[NGRAPH * D];
__device__ float d_cnt[NGRAPH];
__device__ int   d_is64;

// ---------------- dtype detection: int64 vs int32 indices ----------------
// If the harness kept int64 (little-endian, non-negative ids), every odd 32-bit
// word is 0. If it downcast to int32, odd words are dst node ids (~never all 0).
__global__ void detect_kernel(const int* __restrict__ w) {
    if (threadIdx.x == 0 && blockIdx.x == 0) {
        int zeros = 0;
        #pragma unroll
        for (int k = 0; k < 64; k++)
            if (w[2 * k + 1] == 0) zeros++;
        d_is64 = (zeros == 64) ? 1 : 0;
    }
}

// ---------------- index conversion (branch on detected dtype) ----------------
__global__ void cvt_edges_kernel(const void* __restrict__ ei,
                                 int* __restrict__ src, int* __restrict__ dst,
                                 int E, int n) {
    int i = blockIdx.x * blockDim.x + threadIdx.x;
    if (i >= E) return;
    int s, d2;
    if (d_is64) {
        const long long* p = (const long long*)ei;
        s  = (int)p[i];
        d2 = (int)p[(size_t)E + i];
    } else {
        const int* p = (const int*)ei;
        s  = p[i];
        d2 = p[E + i];
    }
    // clamp defensively (wrong dtype guess -> rel_err, not crash)
    s  = min(max(s, 0), n - 1);
    d2 = min(max(d2, 0), n - 1);
    src[i] = s;
    dst[i] = d2;
}

__global__ void cvt_batch_kernel(const void* __restrict__ b,
                                 int* __restrict__ out, int n) {
    int i = blockIdx.x * blockDim.x + threadIdx.x;
    if (i >= n) return;
    int v;
    if (d_is64) v = (int)((const long long*)b)[i];
    else        v = ((const int*)b)[i];
    out[i] = min(max(v, 0), NGRAPH - 1);
}

// ---------------- degree ----------------
__global__ void deg_kernel(const int* __restrict__ dst, float* __restrict__ deg, int E) {
    int i = blockIdx.x * blockDim.x + threadIdx.x;
    if (i < E) atomicAdd(&deg[dst[i]], 1.0f);
}

__global__ void dinv_kernel(const float* __restrict__ deg, float* __restrict__ dinv, int n) {
    int i = blockIdx.x * blockDim.x + threadIdx.x;
    if (i < n) dinv[i] = rsqrtf(deg[i] + 1.0f);
}

// ---------------- GEMM: g = (in @ W) * dinv[row] ----------------
#define XPAD 132
__global__ void __launch_bounds__(256, 2)
gemm_kernel(const float* __restrict__ in, const float* __restrict__ W,
            const float* __restrict__ dinv, float* __restrict__ out, int n) {
    extern __shared__ float sm[];
    float* Wsm = sm;               // 128*128
    float* Xs  = sm + D * D;       // 64*XPAD

    int tid  = threadIdx.x;
    int row0 = blockIdx.x * 64;

    {
        const float4* Wg = (const float4*)W;
        float4* Wd = (float4*)Wsm;
        #pragma unroll
        for (int i = tid; i < D * D / 4; i += 256) Wd[i] = Wg[i];
    }
    for (int i = tid; i < 64 * 32; i += 256) {
        int r = i >> 5, kc = (i & 31);
        float4 v = make_float4(0.f, 0.f, 0.f, 0.f);
        if (row0 + r < n)
            v = *(const float4*)(in + (size_t)(row0 + r) * D + kc * 4);
        *(float4*)&Xs[r * XPAD + kc * 4] = v;
    }
    __syncthreads();

    int ty = tid >> 4;
    int tx = tid & 15;

    float acc[4][8];
    #pragma unroll
    for (int i = 0; i < 4; i++)
        #pragma unroll
        for (int j = 0; j < 8; j++) acc[i][j] = 0.f;

    const float* x0 = &Xs[(ty * 4 + 0) * XPAD];
    const float* x1 = &Xs[(ty * 4 + 1) * XPAD];
    const float* x2 = &Xs[(ty * 4 + 2) * XPAD];
    const float* x3 = &Xs[(ty * 4 + 3) * XPAD];

    #pragma unroll 4
    for (int k = 0; k < D; k++) {
        float xs[4];
        xs[0] = x0[k]; xs[1] = x1[k]; xs[2] = x2[k]; xs[3] = x3[k];
        float4 w0 = *(const float4*)&Wsm[k * D + tx * 8];
        float4 w1 = *(const float4*)&Wsm[k * D + tx * 8 + 4];
        float ws[8] = {w0.x, w0.y, w0.z, w0.w, w1.x, w1.y, w1.z, w1.w};
        #pragma unroll
        for (int i = 0; i < 4; i++)
            #pragma unroll
            for (int j = 0; j < 8; j++)
                acc[i][j] += xs[i] * ws[j];
    }

    #pragma unroll
    for (int i = 0; i < 4; i++) {
        int r = row0 + ty * 4 + i;
        if (r < n) {
            float s = dinv[r];
            float4 o0 = make_float4(acc[i][0]*s, acc[i][1]*s, acc[i][2]*s, acc[i][3]*s);
            float4 o1 = make_float4(acc[i][4]*s, acc[i][5]*s, acc[i][6]*s, acc[i][7]*s);
            float* p = out + (size_t)r * D + tx * 8;
            *(float4*)p       = o0;
            *(float4*)(p + 4) = o1;
        }
    }
}

// ---------------- edge scatter: agg[dst] += g[src] ----------------
#define EDGES_PER_WARP 4
__global__ void edge_kernel(const int* __restrict__ src, const int* __restrict__ dst,
                            const float* __restrict__ g, float* __restrict__ agg, int E) {
    int warp = (blockIdx.x * blockDim.x + threadIdx.x) >> 5;
    int lane = threadIdx.x & 31;
    int e0 = warp * EDGES_PER_WARP;
    #pragma unroll
    for (int q = 0; q < EDGES_PER_WARP; q++) {
        int e = e0 + q;
        if (e < E) {
            int s  = __ldg(&src[e]);
            int d2 = __ldg(&dst[e]);
            float4 v = *(const float4*)(g + (size_t)s * D + lane * 4);
            float* p = agg + (size_t)d2 * D + lane * 4;
            asm volatile("red.global.add.v4.f32 [%0], {%1,%2,%3,%4};"
                         :: "l"(p), "f"(v.x), "f"(v.y), "f"(v.z), "f"(v.w)
                         : "memory");
        }
    }
}

// ---------------- post: t=(agg+g)*dinv+b ; LN ; (+resid) ; (relu) ----------------
__global__ void post_kernel(float* __restrict__ agg, const float* __restrict__ g,
                            const float* __restrict__ resid,
                            const float* __restrict__ dinv,
                            const float* __restrict__ bias,
                            const float* __restrict__ gamma,
                            const float* __restrict__ beta,
                            int n, int do_relu) {
    int warp = (blockIdx.x * blockDim.x + threadIdx.x) >> 5;
    int lane = threadIdx.x & 31;
    if (warp >= n) return;
    size_t base = (size_t)warp * D + lane * 4;
    float s = dinv[warp];

    float4 a  = *(const float4*)(agg + base);
    float4 gg = *(const float4*)(g + base);
    float4 b4 = *(const float4*)(bias + lane * 4);

    float4 t;
    t.x = (a.x + gg.x) * s + b4.x;
    t.y = (a.y + gg.y) * s + b4.y;
    t.z = (a.z + gg.z) * s + b4.z;
    t.w = (a.w + gg.w) * s + b4.w;

    float sum = t.x + t.y + t.z + t.w;
    #pragma unroll
    for (int o = 16; o > 0; o >>= 1) sum += __shfl_xor_sync(0xffffffffu, sum, o);
    float mu = sum * (1.0f / D);

    float dx = t.x - mu, dy = t.y - mu, dz = t.z - mu, dw = t.w - mu;
    float ss = dx*dx + dy*dy + dz*dz + dw*dw;
    #pragma unroll
    for (int o = 16; o > 0; o >>= 1) ss += __shfl_xor_sync(0xffffffffu, ss, o);
    float inv = rsqrtf(ss * (1.0f / D) + LN_EPS);

    float4 g4 = *(const float4*)(gamma + lane * 4);
    float4 e4 = *(const float4*)(beta + lane * 4);

    float4 y;
    y.x = dx * inv * g4.x + e4.x;
    y.y = dy * inv * g4.y + e4.y;
    y.z = dz * inv * g4.z + e4.z;
    y.w = dw * inv * g4.w + e4.w;

    if (resid) {
        float4 r4 = *(const float4*)(resid + base);
        y.x += r4.x; y.y += r4.y; y.z += r4.z; y.w += r4.w;
    }
    if (do_relu) {
        y.x = fmaxf(y.x, 0.f); y.y = fmaxf(y.y, 0.f);
        y.z = fmaxf(y.z, 0.f); y.w = fmaxf(y.w, 0.f);
    }
    *(float4*)(agg + base) = y;
}

// ---------------- pooling ----------------
__global__ void pool_kernel(const float* __restrict__ h, const int* __restrict__ batch,
                            float* __restrict__ pooled, float* __restrict__ cnt, int n) {
    int warp = (blockIdx.x * blockDim.x + threadIdx.x) >> 5;
    int lane = threadIdx.x & 31;
    if (warp >= n) return;
    int b = batch[warp];
    float4 v = *(const float4*)(h + (size_t)warp * D + lane * 4);
    float* p = pooled + (size_t)b * D + lane * 4;
    asm volatile("red.global.add.v4.f32 [%0], {%1,%2,%3,%4};"
                 :: "l"(p), "f"(v.x), "f"(v.y), "f"(v.z), "f"(v.w)
                 : "memory");
    if (lane == 0) atomicAdd(&cnt[b], 1.0f);
}

// ---------------- final readout ----------------
__global__ void out_kernel(const float* __restrict__ pooled, const float* __restrict__ cnt,
                           const float* __restrict__ lin_w, const float* __restrict__ lin_b,
                           float* __restrict__ out, int ngraphs) {
    int warp = (blockIdx.x * blockDim.x + threadIdx.x) >> 5;
    int lane = threadIdx.x & 31;
    if (warp >= ngraphs) return;
    float acc = 0.f;
    #pragma unroll
    for (int q = 0; q < 4; q++) {
        int j = lane + 32 * q;
        acc += pooled[(size_t)warp * D + j] * lin_w[j];
    }
    #pragma unroll
    for (int o = 16; o > 0; o >>= 1) acc += __shfl_xor_sync(0xffffffffu, acc, o);
    if (lane == 0)
        out[warp] = acc / fmaxf(cnt[warp], 1.0f) + lin_b[0];
}

// ---------------- host launcher ----------------
extern "C" void kernel_launch(void* const* d_in, const int* in_sizes, int n_in,
                              void* d_out, int out_size) {
    const float* x      = (const float*)d_in[0];
    const void*  ei     = d_in[1];
    const void*  batch  = d_in[2];
    const float* Ws     = (const float*)d_in[3];
    const float* bs     = (const float*)d_in[4];
    const float* gammas = (const float*)d_in[5];
    const float* betas  = (const float*)d_in[6];
    const float* lin_w  = (const float*)d_in[7];
    const float* lin_b  = (const float*)d_in[8];
    float* out = (float*)d_out;

    int n = in_sizes[2];             // number of nodes (batch vector length)
    int E = in_sizes[1] / 2;         // number of edges
    int ngraphs = out_size;          // [G,1] float32
    if (n > NMAX) n = NMAX;
    if (E > EMAX) E = EMAX;

    float *bufG, *bufA, *bufB, *deg, *dinv, *pooled, *cnt;
    int *src, *dst, *batch32;
    cudaGetSymbolAddress((void**)&bufG,    d_bufG);
    cudaGetSymbolAddress((void**)&bufA,    d_bufA);
    cudaGetSymbolAddress((void**)&bufB,    d_bufB);
    cudaGetSymbolAddress((void**)&deg,     d_deg);
    cudaGetSymbolAddress((void**)&dinv,    d_dinv);
    cudaGetSymbolAddress((void**)&src,     d_src);
    cudaGetSymbolAddress((void**)&dst,     d_dst);
    cudaGetSymbolAddress((void**)&batch32, d_batch32);
    cudaGetSymbolAddress((void**)&pooled,  d_pooled);
    cudaGetSymbolAddress((void**)&cnt,     d_cnt);

    const int smem_bytes = (D * D + 64 * XPAD) * sizeof(float);
    cudaFuncSetAttribute(gemm_kernel, cudaFuncAttributeMaxDynamicSharedMemorySize, smem_bytes);

    // dtype detection + index conversion + degree
    detect_kernel<<<1, 32>>>((const int*)ei);
    cvt_edges_kernel<<<(E + 255) / 256, 256>>>(ei, src, dst, E, n);
    cvt_batch_kernel<<<(n + 255) / 256, 256>>>(batch, batch32, n);
    cudaMemsetAsync(deg, 0, (size_t)n * sizeof(float));
    deg_kernel<<<(E + 255) / 256, 256>>>(dst, deg, E);
    dinv_kernel<<<(n + 255) / 256, 256>>>(deg, dinv, n);

    int gemm_blocks = (n + 63) / 64;
    int row_warp_blocks = (n + 7) / 8;
    long long ewarps = ((long long)E + EDGES_PER_WARP - 1) / EDGES_PER_WARP;
    int edge_blocks = (int)((ewarps * 32 + 255) / 256);

    const float* in_ptr = x;
    float* aggbufs[2] = {bufA, bufB};
    for (int l = 0; l < 4; l++) {
        gemm_kernel<<<gemm_blocks, 256, smem_bytes>>>(in_ptr, Ws + (size_t)l * D * D, dinv, bufG, n);
        float* agg = aggbufs[l & 1];
        cudaMemsetAsync(agg, 0, (size_t)n * D * sizeof(float));
        edge_kernel<<<edge_blocks, 256>>>(src, dst, bufG, agg, E);
        post_kernel<<<row_warp_blocks, 256>>>(agg, bufG,
                                              (l == 0) ? nullptr : in_ptr,
                                              dinv,
                                              bs + l * D, gammas + l * D, betas + l * D,
                                              n, (l < 3) ? 1 : 0);
        in_ptr = agg;
    }

    cudaMemsetAsync(pooled, 0, (size_t)ngraphs * D * sizeof(float));
    cudaMemsetAsync(cnt,    0, (size_t)ngraphs * sizeof(float));
    pool_kernel<<<row_warp_blocks, 256>>>(in_ptr, batch32, pooled, cnt, n);
    out_kernel<<<(ngraphs * 32 + 255) / 256, 256>>>(pooled, cnt, lin_w, lin_b, out, ngraphs);
}

// round 3
// speedup vs baseline: 1.4178x; 1.4178x over previous
#include <cuda_runtime.h>
#include <stdint.h>

#define D 128
#define NMAX 100000
#define EMAX 1600000
#define NGRAPH 512
#define LN_EPS 1e-5f

#define SCAN_TPB 256
#define SCAN_ITEMS 8
#define SCAN_BLOCK (SCAN_TPB * SCAN_ITEMS)   // 2048
#define SCAN_MAXBLOCKS 1024

// ---------------- scratch (no allocs allowed) ----------------
__device__ float d_bufG[(size_t)NMAX * D];   // g = (in @ W) * dinv[row]
__device__ float d_bufA[(size_t)NMAX * D];
__device__ float d_bufB[(size_t)NMAX * D];
__device__ float d_dinv[NMAX];
__device__ int   d_src[EMAX];
__device__ int   d_dst[EMAX];
__device__ int   d_csr_src[EMAX];
__device__ int   d_cnt_int[NMAX];
__device__ int   d_row_start[NMAX + 1];
__device__ int   d_wr_ptr[NMAX];
__device__ int   d_blockSums[SCAN_MAXBLOCKS];
__device__ int   d_batch32[NMAX];
__device__ float d_pooled[NGRAPH * D];
__device__ float d_gcnt[NGRAPH];
__device__ int   d_is64;

// ---------------- dtype detection: int64 vs int32 indices ----------------
__global__ void detect_kernel(const int* __restrict__ w) {
    if (threadIdx.x == 0 && blockIdx.x == 0) {
        int zeros = 0;
        #pragma unroll
        for (int k = 0; k < 64; k++)
            if (w[2 * k + 1] == 0) zeros++;
        d_is64 = (zeros == 64) ? 1 : 0;
    }
}

__global__ void cvt_edges_kernel(const void* __restrict__ ei,
                                 int* __restrict__ src, int* __restrict__ dst,
                                 int E, int n) {
    int i = blockIdx.x * blockDim.x + threadIdx.x;
    if (i >= E) return;
    int s, d2;
    if (d_is64) {
        const long long* p = (const long long*)ei;
        s  = (int)p[i];
        d2 = (int)p[(size_t)E + i];
    } else {
        const int* p = (const int*)ei;
        s  = p[i];
        d2 = p[E + i];
    }
    s  = min(max(s, 0), n - 1);
    d2 = min(max(d2, 0), n - 1);
    src[i] = s;
    dst[i] = d2;
}

__global__ void cvt_batch_kernel(const void* __restrict__ b,
                                 int* __restrict__ out, int n) {
    int i = blockIdx.x * blockDim.x + threadIdx.x;
    if (i >= n) return;
    int v;
    if (d_is64) v = (int)((const long long*)b)[i];
    else        v = ((const int*)b)[i];
    out[i] = min(max(v, 0), NGRAPH - 1);
}

// ---------------- degree histogram (int) ----------------
__global__ void hist_kernel(const int* __restrict__ dst, int* __restrict__ cnt, int E) {
    int i = blockIdx.x * blockDim.x + threadIdx.x;
    if (i < E) atomicAdd(&cnt[dst[i]], 1);
}

__global__ void dinv_kernel(const int* __restrict__ cnt, float* __restrict__ dinv, int n) {
    int i = blockIdx.x * blockDim.x + threadIdx.x;
    if (i < n) dinv[i] = rsqrtf((float)cnt[i] + 1.0f);
}

// ---------------- exclusive scan (3 kernels) ----------------
__global__ void scanA_kernel(const int* __restrict__ cnt, int* __restrict__ row_start,
                             int* __restrict__ blockSums, int n) {
    __shared__ int ssum[SCAN_TPB];
    int b = blockIdx.x, t = threadIdx.x;
    int base = b * SCAN_BLOCK + t * SCAN_ITEMS;
    int v[SCAN_ITEMS];
    int s = 0;
    #pragma unroll
    for (int i = 0; i < SCAN_ITEMS; i++) {
        v[i] = (base + i < n) ? cnt[base + i] : 0;
        s += v[i];
    }
    ssum[t] = s;
    __syncthreads();
    for (int off = 1; off < SCAN_TPB; off <<= 1) {
        int x = (t >= off) ? ssum[t - off] : 0;
        __syncthreads();
        ssum[t] += x;
        __syncthreads();
    }
    int run = ssum[t] - s;   // exclusive prefix of this thread
    #pragma unroll
    for (int i = 0; i < SCAN_ITEMS; i++) {
        if (base + i < n) row_start[base + i] = run;
        run += v[i];
    }
    if (t == SCAN_TPB - 1) blockSums[b] = ssum[t];
}

__global__ void scanB_kernel(int* __restrict__ blockSums, int nb) {
    __shared__ int ssum[SCAN_MAXBLOCKS];
    int t = threadIdx.x;
    int v = (t < nb) ? blockSums[t] : 0;
    ssum[t] = v;
    __syncthreads();
    for (int off = 1; off < SCAN_MAXBLOCKS; off <<= 1) {
        int x = (t >= off) ? ssum[t - off] : 0;
        __syncthreads();
        ssum[t] += x;
        __syncthreads();
    }
    if (t < nb) blockSums[t] = ssum[t] - v;  // exclusive
}

__global__ void scanC_kernel(int* __restrict__ row_start, const int* __restrict__ blockSums,
                             int* __restrict__ wr_ptr, int n, int E) {
    int i = blockIdx.x * blockDim.x + threadIdx.x;
    if (i < n) {
        int v = row_start[i] + blockSums[i / SCAN_BLOCK];
        row_start[i] = v;
        wr_ptr[i] = v;
    }
    if (i == 0) row_start[n] = E;
}

__global__ void scatter_kernel(const int* __restrict__ src, const int* __restrict__ dst,
                               int* __restrict__ wr_ptr, int* __restrict__ csr_src, int E) {
    int e = blockIdx.x * blockDim.x + threadIdx.x;
    if (e < E) {
        int p = atomicAdd(&wr_ptr[dst[e]], 1);
        csr_src[p] = src[e];
    }
}

// ---------------- graph node count histogram ----------------
__global__ void gcnt_kernel(const int* __restrict__ batch, float* __restrict__ gcnt, int n) {
    int i = blockIdx.x * blockDim.x + threadIdx.x;
    if (i < n) atomicAdd(&gcnt[batch[i]], 1.0f);
}

// ---------------- GEMM: g = (in @ W) * dinv[row] ----------------
#define XPAD 132
__global__ void __launch_bounds__(256, 2)
gemm_kernel(const float* __restrict__ in, const float* __restrict__ W,
            const float* __restrict__ dinv, float* __restrict__ out, int n) {
    extern __shared__ float sm[];
    float* Wsm = sm;               // 128*128
    float* Xs  = sm + D * D;       // 64*XPAD

    int tid  = threadIdx.x;
    int row0 = blockIdx.x * 64;

    {
        const float4* Wg = (const float4*)W;
        float4* Wd = (float4*)Wsm;
        #pragma unroll
        for (int i = tid; i < D * D / 4; i += 256) Wd[i] = Wg[i];
    }
    for (int i = tid; i < 64 * 32; i += 256) {
        int r = i >> 5, kc = (i & 31);
        float4 v = make_float4(0.f, 0.f, 0.f, 0.f);
        if (row0 + r < n)
            v = *(const float4*)(in + (size_t)(row0 + r) * D + kc * 4);
        *(float4*)&Xs[r * XPAD + kc * 4] = v;
    }
    __syncthreads();

    int ty = tid >> 4;
    int tx = tid & 15;

    float acc[4][8];
    #pragma unroll
    for (int i = 0; i < 4; i++)
        #pragma unroll
        for (int j = 0; j < 8; j++) acc[i][j] = 0.f;

    const float* x0 = &Xs[(ty * 4 + 0) * XPAD];
    const float* x1 = &Xs[(ty * 4 + 1) * XPAD];
    const float* x2 = &Xs[(ty * 4 + 2) * XPAD];
    const float* x3 = &Xs[(ty * 4 + 3) * XPAD];

    #pragma unroll 4
    for (int k = 0; k < D; k++) {
        float xs[4];
        xs[0] = x0[k]; xs[1] = x1[k]; xs[2] = x2[k]; xs[3] = x3[k];
        float4 w0 = *(const float4*)&Wsm[k * D + tx * 8];
        float4 w1 = *(const float4*)&Wsm[k * D + tx * 8 + 4];
        float ws[8] = {w0.x, w0.y, w0.z, w0.w, w1.x, w1.y, w1.z, w1.w};
        #pragma unroll
        for (int i = 0; i < 4; i++)
            #pragma unroll
            for (int j = 0; j < 8; j++)
                acc[i][j] += xs[i] * ws[j];
    }

    #pragma unroll
    for (int i = 0; i < 4; i++) {
        int r = row0 + ty * 4 + i;
        if (r < n) {
            float s = dinv[r];
            float4 o0 = make_float4(acc[i][0]*s, acc[i][1]*s, acc[i][2]*s, acc[i][3]*s);
            float4 o1 = make_float4(acc[i][4]*s, acc[i][5]*s, acc[i][6]*s, acc[i][7]*s);
            float* p = out + (size_t)r * D + tx * 8;
            *(float4*)p       = o0;
            *(float4*)(p + 4) = o1;
        }
    }
}

// ---------------- fused CSR aggregate + post (LN / resid / relu / pool) ----------------
// one warp per dst row; acc = g[row] + sum_{e in CSR[row]} g[src[e]]
__global__ void __launch_bounds__(256)
agg_post_kernel(const float* __restrict__ g,
                const int* __restrict__ csr_src, const int* __restrict__ row_start,
                const float* __restrict__ resid,
                const float* __restrict__ dinv,
                const float* __restrict__ bias,
                const float* __restrict__ gamma,
                const float* __restrict__ beta,
                float* __restrict__ h_out,
                const int* __restrict__ batch,
                float* __restrict__ pooled,
                int n, int do_relu, int do_pool) {
    int warp = (blockIdx.x * blockDim.x + threadIdx.x) >> 5;
    int lane = threadIdx.x & 31;
    if (warp >= n) return;

    int beg = row_start[warp];
    int end = row_start[warp + 1];
    size_t lo = (size_t)lane * 4;

    float4 acc = *(const float4*)(g + (size_t)warp * D + lo);  // self-loop term

    int e = beg;
    // 4-way unrolled for MLP
    for (; e + 4 <= end; e += 4) {
        int s0 = __ldg(&csr_src[e + 0]);
        int s1 = __ldg(&csr_src[e + 1]);
        int s2 = __ldg(&csr_src[e + 2]);
        int s3 = __ldg(&csr_src[e + 3]);
        float4 v0 = *(const float4*)(g + (size_t)s0 * D + lo);
        float4 v1 = *(const float4*)(g + (size_t)s1 * D + lo);
        float4 v2 = *(const float4*)(g + (size_t)s2 * D + lo);
        float4 v3 = *(const float4*)(g + (size_t)s3 * D + lo);
        acc.x += v0.x + v1.x + v2.x + v3.x;
        acc.y += v0.y + v1.y + v2.y + v3.y;
        acc.z += v0.z + v1.z + v2.z + v3.z;
        acc.w += v0.w + v1.w + v2.w + v3.w;
    }
    for (; e < end; e++) {
        int s = __ldg(&csr_src[e]);
        float4 v = *(const float4*)(g + (size_t)s * D + lo);
        acc.x += v.x; acc.y += v.y; acc.z += v.z; acc.w += v.w;
    }

    float sc = dinv[warp];
    float4 b4 = *(const float4*)(bias + lo);
    float4 t;
    t.x = acc.x * sc + b4.x;
    t.y = acc.y * sc + b4.y;
    t.z = acc.z * sc + b4.z;
    t.w = acc.w * sc + b4.w;

    float sum = t.x + t.y + t.z + t.w;
    #pragma unroll
    for (int o = 16; o > 0; o >>= 1) sum += __shfl_xor_sync(0xffffffffu, sum, o);
    float mu = sum * (1.0f / D);

    float dx = t.x - mu, dy = t.y - mu, dz = t.z - mu, dw = t.w - mu;
    float ss = dx*dx + dy*dy + dz*dz + dw*dw;
    #pragma unroll
    for (int o = 16; o > 0; o >>= 1) ss += __shfl_xor_sync(0xffffffffu, ss, o);
    float inv = rsqrtf(ss * (1.0f / D) + LN_EPS);

    float4 g4 = *(const float4*)(gamma + lo);
    float4 e4 = *(const float4*)(beta + lo);

    float4 y;
    y.x = dx * inv * g4.x + e4.x;
    y.y = dy * inv * g4.y + e4.y;
    y.z = dz * inv * g4.z + e4.z;
    y.w = dw * inv * g4.w + e4.w;

    if (resid) {
        float4 r4 = *(const float4*)(resid + (size_t)warp * D + lo);
        y.x += r4.x; y.y += r4.y; y.z += r4.z; y.w += r4.w;
    }
    if (do_relu) {
        y.x = fmaxf(y.x, 0.f); y.y = fmaxf(y.y, 0.f);
        y.z = fmaxf(y.z, 0.f); y.w = fmaxf(y.w, 0.f);
    }

    if (do_pool) {
        int b = batch[warp];
        float* p = pooled + (size_t)b * D + lo;
        asm volatile("red.global.add.v4.f32 [%0], {%1,%2,%3,%4};"
                     :: "l"(p), "f"(y.x), "f"(y.y), "f"(y.z), "f"(y.w)
                     : "memory");
    } else {
        *(float4*)(h_out + (size_t)warp * D + lo) = y;
    }
}

// ---------------- final readout ----------------
__global__ void out_kernel(const float* __restrict__ pooled, const float* __restrict__ gcnt,
                           const float* __restrict__ lin_w, const float* __restrict__ lin_b,
                           float* __restrict__ out, int ngraphs) {
    int warp = (blockIdx.x * blockDim.x + threadIdx.x) >> 5;
    int lane = threadIdx.x & 31;
    if (warp >= ngraphs) return;
    float acc = 0.f;
    #pragma unroll
    for (int q = 0; q < 4; q++) {
        int j = lane + 32 * q;
        acc += pooled[(size_t)warp * D + j] * lin_w[j];
    }
    #pragma unroll
    for (int o = 16; o > 0; o >>= 1) acc += __shfl_xor_sync(0xffffffffu, acc, o);
    if (lane == 0)
        out[warp] = acc / fmaxf(gcnt[warp], 1.0f) + lin_b[0];
}

// ---------------- host launcher ----------------
extern "C" void kernel_launch(void* const* d_in, const int* in_sizes, int n_in,
                              void* d_out, int out_size) {
    const float* x      = (const float*)d_in[0];
    const void*  ei     = d_in[1];
    const void*  batch  = d_in[2];
    const float* Ws     = (const float*)d_in[3];
    const float* bs     = (const float*)d_in[4];
    const float* gammas = (const float*)d_in[5];
    const float* betas  = (const float*)d_in[6];
    const float* lin_w  = (const float*)d_in[7];
    const float* lin_b  = (const float*)d_in[8];
    float* out = (float*)d_out;

    int n = in_sizes[2];             // number of nodes
    int E = in_sizes[1] / 2;         // number of edges
    int ngraphs = out_size;
    if (n > NMAX) n = NMAX;
    if (E > EMAX) E = EMAX;

    float *bufG, *bufA, *bufB, *dinv, *pooled, *gcnt;
    int *src, *dst, *csr_src, *cnt_int, *row_start, *wr_ptr, *blockSums, *batch32;
    cudaGetSymbolAddress((void**)&bufG,      d_bufG);
    cudaGetSymbolAddress((void**)&bufA,      d_bufA);
    cudaGetSymbolAddress((void**)&bufB,      d_bufB);
    cudaGetSymbolAddress((void**)&dinv,      d_dinv);
    cudaGetSymbolAddress((void**)&src,       d_src);
    cudaGetSymbolAddress((void**)&dst,       d_dst);
    cudaGetSymbolAddress((void**)&csr_src,   d_csr_src);
    cudaGetSymbolAddress((void**)&cnt_int,   d_cnt_int);
    cudaGetSymbolAddress((void**)&row_start, d_row_start);
    cudaGetSymbolAddress((void**)&wr_ptr,    d_wr_ptr);
    cudaGetSymbolAddress((void**)&blockSums, d_blockSums);
    cudaGetSymbolAddress((void**)&batch32,   d_batch32);
    cudaGetSymbolAddress((void**)&pooled,    d_pooled);
    cudaGetSymbolAddress((void**)&gcnt,      d_gcnt);

    const int smem_bytes = (D * D + 64 * XPAD) * sizeof(float);
    cudaFuncSetAttribute(gemm_kernel, cudaFuncAttributeMaxDynamicSharedMemorySize, smem_bytes);

    // ---- preamble: indices, degrees, CSR, graph counts ----
    detect_kernel<<<1, 32>>>((const int*)ei);
    cvt_edges_kernel<<<(E + 255) / 256, 256>>>(ei, src, dst, E, n);
    cvt_batch_kernel<<<(n + 255) / 256, 256>>>(batch, batch32, n);

    cudaMemsetAsync(cnt_int, 0, (size_t)n * sizeof(int));
    hist_kernel<<<(E + 255) / 256, 256>>>(dst, cnt_int, E);
    dinv_kernel<<<(n + 255) / 256, 256>>>(cnt_int, dinv, n);

    int nb = (n + SCAN_BLOCK - 1) / SCAN_BLOCK;
    scanA_kernel<<<nb, SCAN_TPB>>>(cnt_int, row_start, blockSums, n);
    scanB_kernel<<<1, SCAN_MAXBLOCKS>>>(blockSums, nb);
    scanC_kernel<<<(n + 255) / 256, 256>>>(row_start, blockSums, wr_ptr, n, E);
    scatter_kernel<<<(E + 255) / 256, 256>>>(src, dst, wr_ptr, csr_src, E);

    cudaMemsetAsync(gcnt, 0, (size_t)ngraphs * sizeof(float));
    cudaMemsetAsync(pooled, 0, (size_t)ngraphs * D * sizeof(float));
    gcnt_kernel<<<(n + 255) / 256, 256>>>(batch32, gcnt, n);

    // ---- layers ----
    int gemm_blocks = (n + 63) / 64;
    int row_warp_blocks = (n + 7) / 8;
    const float* in_ptr = x;
    float* hbufs[2] = {bufA, bufB};
    for (int l = 0; l < 4; l++) {
        gemm_kernel<<<gemm_blocks, 256, smem_bytes>>>(in_ptr, Ws + (size_t)l * D * D, dinv, bufG, n);
        float* h_out = hbufs[l & 1];
        int do_pool = (l == 3);
        agg_post_kernel<<<row_warp_blocks, 256>>>(bufG, csr_src, row_start,
                                                  (l == 0) ? nullptr : in_ptr,
                                                  dinv,
                                                  bs + l * D, gammas + l * D, betas + l * D,
                                                  h_out, batch32, pooled,
                                                  n, (l < 3) ? 1 : 0, do_pool);
        in_ptr = h_out;
    }

    out_kernel<<<(ngraphs * 32 + 255) / 256, 256>>>(pooled, gcnt, lin_w, lin_b, out, ngraphs);
}

// round 4
// speedup vs baseline: 1.9061x; 1.3445x over previous
#include <cuda_runtime.h>
#include <cuda_bf16.h>
#include <stdint.h>

#define D 128
#define NMAX 100000
#define EMAX 1600000
#define NGRAPH 512
#define LN_EPS 1e-5f

#define SCAN_TPB 256
#define SCAN_ITEMS 8
#define SCAN_BLOCK (SCAN_TPB * SCAN_ITEMS)   // 2048
#define SCAN_MAXBLOCKS 1024

// ---------------- scratch (no allocs allowed) ----------------
__device__ float d_bufG[(size_t)NMAX * D];   // g = (in @ W) * dinv[row]
__device__ float d_bufA[(size_t)NMAX * D];
__device__ float d_bufB[(size_t)NMAX * D];
__device__ float d_dinv[NMAX];
__device__ int   d_src[EMAX];
__device__ int   d_dst[EMAX];
__device__ int   d_csr_src[EMAX];
__device__ int   d_cnt_int[NMAX];
__device__ int   d_row_start[NMAX + 1];
__device__ int   d_wr_ptr[NMAX];
__device__ int   d_blockSums[SCAN_MAXBLOCKS];
__device__ int   d_batch32[NMAX];
__device__ float d_pooled[NGRAPH * D];
__device__ float d_gcnt[NGRAPH];
__device__ int   d_is64;

// ---------------- dtype detection: int64 vs int32 indices ----------------
__global__ void detect_kernel(const int* __restrict__ w) {
    if (threadIdx.x == 0 && blockIdx.x == 0) {
        int zeros = 0;
        #pragma unroll
        for (int k = 0; k < 64; k++)
            if (w[2 * k + 1] == 0) zeros++;
        d_is64 = (zeros == 64) ? 1 : 0;
    }
}

__global__ void cvt_edges_kernel(const void* __restrict__ ei,
                                 int* __restrict__ src, int* __restrict__ dst,
                                 int E, int n) {
    int i = blockIdx.x * blockDim.x + threadIdx.x;
    if (i >= E) return;
    int s, d2;
    if (d_is64) {
        const long long* p = (const long long*)ei;
        s  = (int)p[i];
        d2 = (int)p[(size_t)E + i];
    } else {
        const int* p = (const int*)ei;
        s  = p[i];
        d2 = p[E + i];
    }
    s  = min(max(s, 0), n - 1);
    d2 = min(max(d2, 0), n - 1);
    src[i] = s;
    dst[i] = d2;
}

__global__ void cvt_batch_kernel(const void* __restrict__ b,
                                 int* __restrict__ out, int n) {
    int i = blockIdx.x * blockDim.x + threadIdx.x;
    if (i >= n) return;
    int v;
    if (d_is64) v = (int)((const long long*)b)[i];
    else        v = ((const int*)b)[i];
    out[i] = min(max(v, 0), NGRAPH - 1);
}

// ---------------- degree histogram (int) ----------------
__global__ void hist_kernel(const int* __restrict__ dst, int* __restrict__ cnt, int E) {
    int i = blockIdx.x * blockDim.x + threadIdx.x;
    if (i < E) atomicAdd(&cnt[dst[i]], 1);
}

__global__ void dinv_kernel(const int* __restrict__ cnt, float* __restrict__ dinv, int n) {
    int i = blockIdx.x * blockDim.x + threadIdx.x;
    if (i < n) dinv[i] = rsqrtf((float)cnt[i] + 1.0f);
}

// ---------------- exclusive scan (3 kernels) ----------------
__global__ void scanA_kernel(const int* __restrict__ cnt, int* __restrict__ row_start,
                             int* __restrict__ blockSums, int n) {
    __shared__ int ssum[SCAN_TPB];
    int b = blockIdx.x, t = threadIdx.x;
    int base = b * SCAN_BLOCK + t * SCAN_ITEMS;
    int v[SCAN_ITEMS];
    int s = 0;
    #pragma unroll
    for (int i = 0; i < SCAN_ITEMS; i++) {
        v[i] = (base + i < n) ? cnt[base + i] : 0;
        s += v[i];
    }
    ssum[t] = s;
    __syncthreads();
    for (int off = 1; off < SCAN_TPB; off <<= 1) {
        int x = (t >= off) ? ssum[t - off] : 0;
        __syncthreads();
        ssum[t] += x;
        __syncthreads();
    }
    int run = ssum[t] - s;
    #pragma unroll
    for (int i = 0; i < SCAN_ITEMS; i++) {
        if (base + i < n) row_start[base + i] = run;
        run += v[i];
    }
    if (t == SCAN_TPB - 1) blockSums[b] = ssum[t];
}

__global__ void scanB_kernel(int* __restrict__ blockSums, int nb) {
    __shared__ int ssum[SCAN_MAXBLOCKS];
    int t = threadIdx.x;
    int v = (t < nb) ? blockSums[t] : 0;
    ssum[t] = v;
    __syncthreads();
    for (int off = 1; off < SCAN_MAXBLOCKS; off <<= 1) {
        int x = (t >= off) ? ssum[t - off] : 0;
        __syncthreads();
        ssum[t] += x;
        __syncthreads();
    }
    if (t < nb) blockSums[t] = ssum[t] - v;
}

__global__ void scanC_kernel(int* __restrict__ row_start, const int* __restrict__ blockSums,
                             int* __restrict__ wr_ptr, int n, int E) {
    int i = blockIdx.x * blockDim.x + threadIdx.x;
    if (i < n) {
        int v = row_start[i] + blockSums[i / SCAN_BLOCK];
        row_start[i] = v;
        wr_ptr[i] = v;
    }
    if (i == 0) row_start[n] = E;
}

__global__ void scatter_kernel(const int* __restrict__ src, const int* __restrict__ dst,
                               int* __restrict__ wr_ptr, int* __restrict__ csr_src, int E) {
    int e = blockIdx.x * blockDim.x + threadIdx.x;
    if (e < E) {
        int p = atomicAdd(&wr_ptr[dst[e]], 1);
        csr_src[p] = src[e];
    }
}

__global__ void gcnt_kernel(const int* __restrict__ batch, float* __restrict__ gcnt, int n) {
    int i = blockIdx.x * blockDim.x + threadIdx.x;
    if (i < n) atomicAdd(&gcnt[batch[i]], 1.0f);
}

// ---------------- tensor-core GEMM: g = (in @ W) * dinv[row] ----------------
// bf16 hi/lo split: X@W ~= Xh@Wh + Xh@Wl + Xl@Wh (rel err ~2^-17)
// CTA: 64 rows x 128 cols, 8 warps (2x4), warp tile 32x32 (2x4 m16n8k16 tiles)
#define WPAD 136   // bf16 elems per padded row (272 B: conflict-free ldmatrix)

__device__ __forceinline__ void ldsm_x4(uint32_t* r, uint32_t addr) {
    asm volatile("ldmatrix.sync.aligned.m8n8.x4.shared.b16 {%0,%1,%2,%3}, [%4];"
                 : "=r"(r[0]), "=r"(r[1]), "=r"(r[2]), "=r"(r[3]) : "r"(addr));
}
__device__ __forceinline__ void ldsm_x4t(uint32_t* r, uint32_t addr) {
    asm volatile("ldmatrix.sync.aligned.m8n8.x4.trans.shared.b16 {%0,%1,%2,%3}, [%4];"
                 : "=r"(r[0]), "=r"(r[1]), "=r"(r[2]), "=r"(r[3]) : "r"(addr));
}
__device__ __forceinline__ void mma_bf16(float* c, const uint32_t* a, const uint32_t* b) {
    asm volatile("mma.sync.aligned.m16n8k16.row.col.f32.bf16.bf16.f32 "
                 "{%0,%1,%2,%3}, {%4,%5,%6,%7}, {%8,%9}, {%0,%1,%2,%3};"
                 : "+f"(c[0]), "+f"(c[1]), "+f"(c[2]), "+f"(c[3])
                 : "r"(a[0]), "r"(a[1]), "r"(a[2]), "r"(a[3]), "r"(b[0]), "r"(b[1]));
}

__global__ void __launch_bounds__(256, 2)
gemm_kernel(const float* __restrict__ in, const float* __restrict__ W,
            const float* __restrict__ dinv, float* __restrict__ out, int n) {
    extern __shared__ __nv_bfloat16 sm[];
    __nv_bfloat16* Wh = sm;                     // [128][WPAD]
    __nv_bfloat16* Wl = Wh + 128 * WPAD;
    __nv_bfloat16* Xh = Wl + 128 * WPAD;        // [64][WPAD]
    __nv_bfloat16* Xl = Xh + 64 * WPAD;

    int tid  = threadIdx.x;
    int row0 = blockIdx.x * 64;

    // stage W -> bf16 hi/lo (128x128, 16 float4 per thread)
    #pragma unroll
    for (int i = tid; i < 128 * 32; i += 256) {
        int r = i >> 5, c = (i & 31) * 4;
        float4 w = *(const float4*)(W + r * D + c);
        __nv_bfloat16 h0 = __float2bfloat16(w.x);
        __nv_bfloat16 h1 = __float2bfloat16(w.y);
        __nv_bfloat16 h2 = __float2bfloat16(w.z);
        __nv_bfloat16 h3 = __float2bfloat16(w.w);
        __nv_bfloat16* ph = Wh + r * WPAD + c;
        __nv_bfloat16* pl = Wl + r * WPAD + c;
        ph[0] = h0; ph[1] = h1; ph[2] = h2; ph[3] = h3;
        pl[0] = __float2bfloat16(w.x - __bfloat162float(h0));
        pl[1] = __float2bfloat16(w.y - __bfloat162float(h1));
        pl[2] = __float2bfloat16(w.z - __bfloat162float(h2));
        pl[3] = __float2bfloat16(w.w - __bfloat162float(h3));
    }
    // stage X tile -> bf16 hi/lo (64x128, 8 float4 per thread)
    #pragma unroll
    for (int i = tid; i < 64 * 32; i += 256) {
        int r = i >> 5, c = (i & 31) * 4;
        float4 v = make_float4(0.f, 0.f, 0.f, 0.f);
        if (row0 + r < n)
            v = *(const float4*)(in + (size_t)(row0 + r) * D + c);
        __nv_bfloat16 h0 = __float2bfloat16(v.x);
        __nv_bfloat16 h1 = __float2bfloat16(v.y);
        __nv_bfloat16 h2 = __float2bfloat16(v.z);
        __nv_bfloat16 h3 = __float2bfloat16(v.w);
        __nv_bfloat16* ph = Xh + r * WPAD + c;
        __nv_bfloat16* pl = Xl + r * WPAD + c;
        ph[0] = h0; ph[1] = h1; ph[2] = h2; ph[3] = h3;
        pl[0] = __float2bfloat16(v.x - __bfloat162float(h0));
        pl[1] = __float2bfloat16(v.y - __bfloat162float(h1));
        pl[2] = __float2bfloat16(v.z - __bfloat162float(h2));
        pl[3] = __float2bfloat16(v.w - __bfloat162float(h3));
    }
    __syncthreads();

    int wid  = tid >> 5;
    int lane = tid & 31;
    int wm = wid >> 2;        // 0..1 : rows wm*32
    int wn = wid & 3;         // 0..3 : cols wn*32

    int l7  = lane & 7;
    int lb3 = (lane >> 3) & 1;
    int lb4 = (lane >> 4) & 1;

    float acc[2][4][4];
    #pragma unroll
    for (int mt = 0; mt < 2; mt++)
        #pragma unroll
        for (int nt = 0; nt < 4; nt++)
            #pragma unroll
            for (int q = 0; q < 4; q++) acc[mt][nt][q] = 0.f;

    #pragma unroll
    for (int kk = 0; kk < 8; kk++) {
        int k0 = kk * 16;
        uint32_t ah[2][4], al[2][4];
        #pragma unroll
        for (int mt = 0; mt < 2; mt++) {
            int r = wm * 32 + mt * 16 + l7 + lb3 * 8;
            int c = k0 + lb4 * 8;
            ldsm_x4(ah[mt], (uint32_t)__cvta_generic_to_shared(Xh + r * WPAD + c));
            ldsm_x4(al[mt], (uint32_t)__cvta_generic_to_shared(Xl + r * WPAD + c));
        }
        uint32_t bh[4][2], bl[4][2];
        #pragma unroll
        for (int p = 0; p < 2; p++) {
            int r = k0 + l7 + lb3 * 8;
            int c = wn * 32 + p * 16 + lb4 * 8;
            uint32_t t[4];
            ldsm_x4t(t, (uint32_t)__cvta_generic_to_shared(Wh + r * WPAD + c));
            bh[2*p][0] = t[0]; bh[2*p][1] = t[1]; bh[2*p+1][0] = t[2]; bh[2*p+1][1] = t[3];
            ldsm_x4t(t, (uint32_t)__cvta_generic_to_shared(Wl + r * WPAD + c));
            bl[2*p][0] = t[0]; bl[2*p][1] = t[1]; bl[2*p+1][0] = t[2]; bl[2*p+1][1] = t[3];
        }
        #pragma unroll
        for (int mt = 0; mt < 2; mt++)
            #pragma unroll
            for (int nt = 0; nt < 4; nt++) {
                mma_bf16(acc[mt][nt], ah[mt], bh[nt]);
                mma_bf16(acc[mt][nt], ah[mt], bl[nt]);
                mma_bf16(acc[mt][nt], al[mt], bh[nt]);
            }
    }

    // epilogue: scale by dinv[row], store
    int quad = lane >> 2;
    int tcol = (lane & 3) * 2;
    #pragma unroll
    for (int mt = 0; mt < 2; mt++) {
        int r_lo = row0 + wm * 32 + mt * 16 + quad;
        int r_hi = r_lo + 8;
        float s_lo = (r_lo < n) ? dinv[r_lo] : 0.f;
        float s_hi = (r_hi < n) ? dinv[r_hi] : 0.f;
        #pragma unroll
        for (int nt = 0; nt < 4; nt++) {
            int c = wn * 32 + nt * 8 + tcol;
            if (r_lo < n) {
                float2 v = make_float2(acc[mt][nt][0] * s_lo, acc[mt][nt][1] * s_lo);
                *(float2*)(out + (size_t)r_lo * D + c) = v;
            }
            if (r_hi < n) {
                float2 v = make_float2(acc[mt][nt][2] * s_hi, acc[mt][nt][3] * s_hi);
                *(float2*)(out + (size_t)r_hi * D + c) = v;
            }
        }
    }
}

// ---------------- fused CSR aggregate + post (LN / resid / relu / pool) ----------------
__global__ void __launch_bounds__(256)
agg_post_kernel(const float* __restrict__ g,
                const int* __restrict__ csr_src, const int* __restrict__ row_start,
                const float* __restrict__ resid,
                const float* __restrict__ dinv,
                const float* __restrict__ bias,
                const float* __restrict__ gamma,
                const float* __restrict__ beta,
                float* __restrict__ h_out,
                const int* __restrict__ batch,
                float* __restrict__ pooled,
                int n, int do_relu, int do_pool) {
    int warp = (blockIdx.x * blockDim.x + threadIdx.x) >> 5;
    int lane = threadIdx.x & 31;
    if (warp >= n) return;

    int beg = row_start[warp];
    int end = row_start[warp + 1];
    size_t lo = (size_t)lane * 4;

    float4 acc = *(const float4*)(g + (size_t)warp * D + lo);

    int e = beg;
    for (; e + 4 <= end; e += 4) {
        int s0 = __ldg(&csr_src[e + 0]);
        int s1 = __ldg(&csr_src[e + 1]);
        int s2 = __ldg(&csr_src[e + 2]);
        int s3 = __ldg(&csr_src[e + 3]);
        float4 v0 = *(const float4*)(g + (size_t)s0 * D + lo);
        float4 v1 = *(const float4*)(g + (size_t)s1 * D + lo);
        float4 v2 = *(const float4*)(g + (size_t)s2 * D + lo);
        float4 v3 = *(const float4*)(g + (size_t)s3 * D + lo);
        acc.x += v0.x + v1.x + v2.x + v3.x;
        acc.y += v0.y + v1.y + v2.y + v3.y;
        acc.z += v0.z + v1.z + v2.z + v3.z;
        acc.w += v0.w + v1.w + v2.w + v3.w;
    }
    for (; e < end; e++) {
        int s = __ldg(&csr_src[e]);
        float4 v = *(const float4*)(g + (size_t)s * D + lo);
        acc.x += v.x; acc.y += v.y; acc.z += v.z; acc.w += v.w;
    }

    float sc = dinv[warp];
    float4 b4 = *(const float4*)(bias + lo);
    float4 t;
    t.x = acc.x * sc + b4.x;
    t.y = acc.y * sc + b4.y;
    t.z = acc.z * sc + b4.z;
    t.w = acc.w * sc + b4.w;

    float sum = t.x + t.y + t.z + t.w;
    #pragma unroll
    for (int o = 16; o > 0; o >>= 1) sum += __shfl_xor_sync(0xffffffffu, sum, o);
    float mu = sum * (1.0f / D);

    float dx = t.x - mu, dy = t.y - mu, dz = t.z - mu, dw = t.w - mu;
    float ss = dx*dx + dy*dy + dz*dz + dw*dw;
    #pragma unroll
    for (int o = 16; o > 0; o >>= 1) ss += __shfl_xor_sync(0xffffffffu, ss, o);
    float inv = rsqrtf(ss * (1.0f / D) + LN_EPS);

    float4 g4 = *(const float4*)(gamma + lo);
    float4 e4 = *(const float4*)(beta + lo);

    float4 y;
    y.x = dx * inv * g4.x + e4.x;
    y.y = dy * inv * g4.y + e4.y;
    y.z = dz * inv * g4.z + e4.z;
    y.w = dw * inv * g4.w + e4.w;

    if (resid) {
        float4 r4 = *(const float4*)(resid + (size_t)warp * D + lo);
        y.x += r4.x; y.y += r4.y; y.z += r4.z; y.w += r4.w;
    }
    if (do_relu) {
        y.x = fmaxf(y.x, 0.f); y.y = fmaxf(y.y, 0.f);
        y.z = fmaxf(y.z, 0.f); y.w = fmaxf(y.w, 0.f);
    }

    if (do_pool) {
        int b = batch[warp];
        float* p = pooled + (size_t)b * D + lo;
        asm volatile("red.global.add.v4.f32 [%0], {%1,%2,%3,%4};"
                     :: "l"(p), "f"(y.x), "f"(y.y), "f"(y.z), "f"(y.w)
                     : "memory");
    } else {
        *(float4*)(h_out + (size_t)warp * D + lo) = y;
    }
}

// ---------------- final readout ----------------
__global__ void out_kernel(const float* __restrict__ pooled, const float* __restrict__ gcnt,
                           const float* __restrict__ lin_w, const float* __restrict__ lin_b,
                           float* __restrict__ out, int ngraphs) {
    int warp = (blockIdx.x * blockDim.x + threadIdx.x) >> 5;
    int lane = threadIdx.x & 31;
    if (warp >= ngraphs) return;
    float acc = 0.f;
    #pragma unroll
    for (int q = 0; q < 4; q++) {
        int j = lane + 32 * q;
        acc += pooled[(size_t)warp * D + j] * lin_w[j];
    }
    #pragma unroll
    for (int o = 16; o > 0; o >>= 1) acc += __shfl_xor_sync(0xffffffffu, acc, o);
    if (lane == 0)
        out[warp] = acc / fmaxf(gcnt[warp], 1.0f) + lin_b[0];
}

// ---------------- host launcher ----------------
extern "C" void kernel_launch(void* const* d_in, const int* in_sizes, int n_in,
                              void* d_out, int out_size) {
    const float* x      = (const float*)d_in[0];
    const void*  ei     = d_in[1];
    const void*  batch  = d_in[2];
    const float* Ws     = (const float*)d_in[3];
    const float* bs     = (const float*)d_in[4];
    const float* gammas = (const float*)d_in[5];
    const float* betas  = (const float*)d_in[6];
    const float* lin_w  = (const float*)d_in[7];
    const float* lin_b  = (const float*)d_in[8];
    float* out = (float*)d_out;

    int n = in_sizes[2];
    int E = in_sizes[1] / 2;
    int ngraphs = out_size;
    if (n > NMAX) n = NMAX;
    if (E > EMAX) E = EMAX;

    float *bufG, *bufA, *bufB, *dinv, *pooled, *gcnt;
    int *src, *dst, *csr_src, *cnt_int, *row_start, *wr_ptr, *blockSums, *batch32;
    cudaGetSymbolAddress((void**)&bufG,      d_bufG);
    cudaGetSymbolAddress((void**)&bufA,      d_bufA);
    cudaGetSymbolAddress((void**)&bufB,      d_bufB);
    cudaGetSymbolAddress((void**)&dinv,      d_dinv);
    cudaGetSymbolAddress((void**)&src,       d_src);
    cudaGetSymbolAddress((void**)&dst,       d_dst);
    cudaGetSymbolAddress((void**)&csr_src,   d_csr_src);
    cudaGetSymbolAddress((void**)&cnt_int,   d_cnt_int);
    cudaGetSymbolAddress((void**)&row_start, d_row_start);
    cudaGetSymbolAddress((void**)&wr_ptr,    d_wr_ptr);
    cudaGetSymbolAddress((void**)&blockSums, d_blockSums);
    cudaGetSymbolAddress((void**)&batch32,   d_batch32);
    cudaGetSymbolAddress((void**)&pooled,    d_pooled);
    cudaGetSymbolAddress((void**)&gcnt,      d_gcnt);

    const int smem_bytes = (2 * 128 * WPAD + 2 * 64 * WPAD) * sizeof(__nv_bfloat16);
    cudaFuncSetAttribute(gemm_kernel, cudaFuncAttributeMaxDynamicSharedMemorySize, smem_bytes);

    // ---- preamble ----
    detect_kernel<<<1, 32>>>((const int*)ei);
    cvt_edges_kernel<<<(E + 255) / 256, 256>>>(ei, src, dst, E, n);
    cvt_batch_kernel<<<(n + 255) / 256, 256>>>(batch, batch32, n);

    cudaMemsetAsync(cnt_int, 0, (size_t)n * sizeof(int));
    hist_kernel<<<(E + 255) / 256, 256>>>(dst, cnt_int, E);
    dinv_kernel<<<(n + 255) / 256, 256>>>(cnt_int, dinv, n);

    int nb = (n + SCAN_BLOCK - 1) / SCAN_BLOCK;
    scanA_kernel<<<nb, SCAN_TPB>>>(cnt_int, row_start, blockSums, n);
    scanB_kernel<<<1, SCAN_MAXBLOCKS>>>(blockSums, nb);
    scanC_kernel<<<(n + 255) / 256, 256>>>(row_start, blockSums, wr_ptr, n, E);
    scatter_kernel<<<(E + 255) / 256, 256>>>(src, dst, wr_ptr, csr_src, E);

    cudaMemsetAsync(gcnt, 0, (size_t)ngraphs * sizeof(float));
    cudaMemsetAsync(pooled, 0, (size_t)ngraphs * D * sizeof(float));
    gcnt_kernel<<<(n + 255) / 256, 256>>>(batch32, gcnt, n);

    // ---- layers ----
    int gemm_blocks = (n + 63) / 64;
    int row_warp_blocks = (n + 7) / 8;
    const float* in_ptr = x;
    float* hbufs[2] = {bufA, bufB};
    for (int l = 0; l < 4; l++) {
        gemm_kernel<<<gemm_blocks, 256, smem_bytes>>>(in_ptr, Ws + (size_t)l * D * D, dinv, bufG, n);
        float* h_out = hbufs[l & 1];
        int do_pool = (l == 3);
        agg_post_kernel<<<row_warp_blocks, 256>>>(bufG, csr_src, row_start,
                                                  (l == 0) ? nullptr : in_ptr,
                                                  dinv,
                                                  bs + l * D, gammas + l * D, betas + l * D,
                                                  h_out, batch32, pooled,
                                                  n, (l < 3) ? 1 : 0, do_pool);
        in_ptr = h_out;
    }

    out_kernel<<<(ngraphs * 32 + 255) / 256, 256>>>(pooled, gcnt, lin_w, lin_b, out, ngraphs);
}

// round 5
// speedup vs baseline: 2.2607x; 1.1860x over previous
#include <cuda_runtime.h>
#include <cuda_bf16.h>
#include <stdint.h>

#define D 128
#define NMAX 100000
#define EMAX 1600000
#define NGRAPH 512
#define LN_EPS 1e-5f

#define SCAN_TPB 256
#define SCAN_ITEMS 8
#define SCAN_BLOCK (SCAN_TPB * SCAN_ITEMS)   // 2048
#define SCAN_MAXBLOCKS 1024

// ---------------- scratch (no allocs allowed) ----------------
__device__ float d_bufG[(size_t)NMAX * D];   // g = (in @ W) * dinv[row]
__device__ float d_bufA[(size_t)NMAX * D];
__device__ float d_bufB[(size_t)NMAX * D];
__device__ float d_dinv[NMAX];
__device__ int   d_src[EMAX];
__device__ int   d_dst[EMAX];
__device__ int   d_csr_src[EMAX];
__device__ int   d_cnt_int[NMAX];
__device__ int   d_row_start[NMAX + 1];
__device__ int   d_wr_ptr[NMAX];
__device__ int   d_blockSums[SCAN_MAXBLOCKS];
__device__ int   d_batch32[NMAX];
__device__ float d_pooled[NGRAPH * D];
__device__ float d_gcnt[NGRAPH];
__device__ int   d_is64;

// ---------------- dtype detection: int64 vs int32 indices ----------------
__global__ void detect_kernel(const int* __restrict__ w) {
    if (threadIdx.x == 0 && blockIdx.x == 0) {
        int zeros = 0;
        #pragma unroll
        for (int k = 0; k < 64; k++)
            if (w[2 * k + 1] == 0) zeros++;
        d_is64 = (zeros == 64) ? 1 : 0;
    }
}

// ---------------- fused: convert edges + degree histogram ----------------
__global__ void cvt_hist_kernel(const void* __restrict__ ei,
                                int* __restrict__ src, int* __restrict__ dst,
                                int* __restrict__ cnt, int E, int n) {
    int i = blockIdx.x * blockDim.x + threadIdx.x;
    if (i >= E) return;
    int s, d2;
    if (d_is64) {
        const long long* p = (const long long*)ei;
        s  = (int)p[i];
        d2 = (int)p[(size_t)E + i];
    } else {
        const int* p = (const int*)ei;
        s  = p[i];
        d2 = p[E + i];
    }
    s  = min(max(s, 0), n - 1);
    d2 = min(max(d2, 0), n - 1);
    src[i] = s;
    dst[i] = d2;
    atomicAdd(&cnt[d2], 1);
}

// ---------------- fused: convert batch + graph counts ----------------
__global__ void cvt_batch_kernel(const void* __restrict__ b,
                                 int* __restrict__ outb,
                                 float* __restrict__ gcnt, int n) {
    int i = blockIdx.x * blockDim.x + threadIdx.x;
    if (i >= n) return;
    int v;
    if (d_is64) v = (int)((const long long*)b)[i];
    else        v = ((const int*)b)[i];
    v = min(max(v, 0), NGRAPH - 1);
    outb[i] = v;
    atomicAdd(&gcnt[v], 1.0f);
}

// ---------------- exclusive scan (3 kernels) ----------------
__global__ void scanA_kernel(const int* __restrict__ cnt, int* __restrict__ row_start,
                             int* __restrict__ blockSums, int n) {
    __shared__ int ssum[SCAN_TPB];
    int b = blockIdx.x, t = threadIdx.x;
    int base = b * SCAN_BLOCK + t * SCAN_ITEMS;
    int v[SCAN_ITEMS];
    int s = 0;
    #pragma unroll
    for (int i = 0; i < SCAN_ITEMS; i++) {
        v[i] = (base + i < n) ? cnt[base + i] : 0;
        s += v[i];
    }
    ssum[t] = s;
    __syncthreads();
    for (int off = 1; off < SCAN_TPB; off <<= 1) {
        int x = (t >= off) ? ssum[t - off] : 0;
        __syncthreads();
        ssum[t] += x;
        __syncthreads();
    }
    int run = ssum[t] - s;
    #pragma unroll
    for (int i = 0; i < SCAN_ITEMS; i++) {
        if (base + i < n) row_start[base + i] = run;
        run += v[i];
    }
    if (t == SCAN_TPB - 1) blockSums[b] = ssum[t];
}

__global__ void scanB_kernel(int* __restrict__ blockSums, int nb) {
    __shared__ int ssum[SCAN_MAXBLOCKS];
    int t = threadIdx.x;
    int v = (t < nb) ? blockSums[t] : 0;
    ssum[t] = v;
    __syncthreads();
    for (int off = 1; off < SCAN_MAXBLOCKS; off <<= 1) {
        int x = (t >= off) ? ssum[t - off] : 0;
        __syncthreads();
        ssum[t] += x;
        __syncthreads();
    }
    if (t < nb) blockSums[t] = ssum[t] - v;
}

// fused: finalize row_start + wr_ptr + dinv
__global__ void scanC_kernel(int* __restrict__ row_start, const int* __restrict__ blockSums,
                             int* __restrict__ wr_ptr, const int* __restrict__ cnt,
                             float* __restrict__ dinv, int n, int E) {
    int i = blockIdx.x * blockDim.x + threadIdx.x;
    if (i < n) {
        int v = row_start[i] + blockSums[i / SCAN_BLOCK];
        row_start[i] = v;
        wr_ptr[i] = v;
        dinv[i] = rsqrtf((float)cnt[i] + 1.0f);
    }
    if (i == 0) row_start[n] = E;
}

__global__ void scatter_kernel(const int* __restrict__ src, const int* __restrict__ dst,
                               int* __restrict__ wr_ptr, int* __restrict__ csr_src, int E) {
    int e = blockIdx.x * blockDim.x + threadIdx.x;
    if (e < E) {
        int p = atomicAdd(&wr_ptr[dst[e]], 1);
        csr_src[p] = src[e];
    }
}

// ---------------- tensor-core GEMM: g = (in @ W) * dinv[row] ----------------
#define WPAD 136   // bf16 elems per padded row (272 B: conflict-free ldmatrix)

__device__ __forceinline__ void ldsm_x4(uint32_t* r, uint32_t addr) {
    asm volatile("ldmatrix.sync.aligned.m8n8.x4.shared.b16 {%0,%1,%2,%3}, [%4];"
                 : "=r"(r[0]), "=r"(r[1]), "=r"(r[2]), "=r"(r[3]) : "r"(addr));
}
__device__ __forceinline__ void ldsm_x4t(uint32_t* r, uint32_t addr) {
    asm volatile("ldmatrix.sync.aligned.m8n8.x4.trans.shared.b16 {%0,%1,%2,%3}, [%4];"
                 : "=r"(r[0]), "=r"(r[1]), "=r"(r[2]), "=r"(r[3]) : "r"(addr));
}
__device__ __forceinline__ void mma_bf16(float* c, const uint32_t* a, const uint32_t* b) {
    asm volatile("mma.sync.aligned.m16n8k16.row.col.f32.bf16.bf16.f32 "
                 "{%0,%1,%2,%3}, {%4,%5,%6,%7}, {%8,%9}, {%0,%1,%2,%3};"
                 : "+f"(c[0]), "+f"(c[1]), "+f"(c[2]), "+f"(c[3])
                 : "r"(a[0]), "r"(a[1]), "r"(a[2]), "r"(a[3]), "r"(b[0]), "r"(b[1]));
}

__global__ void __launch_bounds__(256, 2)
gemm_kernel(const float* __restrict__ in, const float* __restrict__ W,
            const float* __restrict__ dinv, float* __restrict__ out, int n) {
    extern __shared__ __nv_bfloat16 sm[];
    __nv_bfloat16* Wh = sm;                     // [128][WPAD]
    __nv_bfloat16* Wl = Wh + 128 * WPAD;
    __nv_bfloat16* Xh = Wl + 128 * WPAD;        // [64][WPAD]
    __nv_bfloat16* Xl = Xh + 64 * WPAD;

    int tid  = threadIdx.x;
    int row0 = blockIdx.x * 64;

    #pragma unroll
    for (int i = tid; i < 128 * 32; i += 256) {
        int r = i >> 5, c = (i & 31) * 4;
        float4 w = *(const float4*)(W + r * D + c);
        __nv_bfloat16 h0 = __float2bfloat16(w.x);
        __nv_bfloat16 h1 = __float2bfloat16(w.y);
        __nv_bfloat16 h2 = __float2bfloat16(w.z);
        __nv_bfloat16 h3 = __float2bfloat16(w.w);
        __nv_bfloat16* ph = Wh + r * WPAD + c;
        __nv_bfloat16* pl = Wl + r * WPAD + c;
        ph[0] = h0; ph[1] = h1; ph[2] = h2; ph[3] = h3;
        pl[0] = __float2bfloat16(w.x - __bfloat162float(h0));
        pl[1] = __float2bfloat16(w.y - __bfloat162float(h1));
        pl[2] = __float2bfloat16(w.z - __bfloat162float(h2));
        pl[3] = __float2bfloat16(w.w - __bfloat162float(h3));
    }
    #pragma unroll
    for (int i = tid; i < 64 * 32; i += 256) {
        int r = i >> 5, c = (i & 31) * 4;
        float4 v = make_float4(0.f, 0.f, 0.f, 0.f);
        if (row0 + r < n)
            v = *(const float4*)(in + (size_t)(row0 + r) * D + c);
        __nv_bfloat16 h0 = __float2bfloat16(v.x);
        __nv_bfloat16 h1 = __float2bfloat16(v.y);
        __nv_bfloat16 h2 = __float2bfloat16(v.z);
        __nv_bfloat16 h3 = __float2bfloat16(v.w);
        __nv_bfloat16* ph = Xh + r * WPAD + c;
        __nv_bfloat16* pl = Xl + r * WPAD + c;
        ph[0] = h0; ph[1] = h1; ph[2] = h2; ph[3] = h3;
        pl[0] = __float2bfloat16(v.x - __bfloat162float(h0));
        pl[1] = __float2bfloat16(v.y - __bfloat162float(h1));
        pl[2] = __float2bfloat16(v.z - __bfloat162float(h2));
        pl[3] = __float2bfloat16(v.w - __bfloat162float(h3));
    }
    __syncthreads();

    int wid  = tid >> 5;
    int lane = tid & 31;
    int wm = wid >> 2;
    int wn = wid & 3;

    int l7  = lane & 7;
    int lb3 = (lane >> 3) & 1;
    int lb4 = (lane >> 4) & 1;

    float acc[2][4][4];
    #pragma unroll
    for (int mt = 0; mt < 2; mt++)
        #pragma unroll
        for (int nt = 0; nt < 4; nt++)
            #pragma unroll
            for (int q = 0; q < 4; q++) acc[mt][nt][q] = 0.f;

    #pragma unroll
    for (int kk = 0; kk < 8; kk++) {
        int k0 = kk * 16;
        uint32_t ah[2][4], al[2][4];
        #pragma unroll
        for (int mt = 0; mt < 2; mt++) {
            int r = wm * 32 + mt * 16 + l7 + lb3 * 8;
            int c = k0 + lb4 * 8;
            ldsm_x4(ah[mt], (uint32_t)__cvta_generic_to_shared(Xh + r * WPAD + c));
            ldsm_x4(al[mt], (uint32_t)__cvta_generic_to_shared(Xl + r * WPAD + c));
        }
        uint32_t bh[4][2], bl[4][2];
        #pragma unroll
        for (int p = 0; p < 2; p++) {
            int r = k0 + l7 + lb3 * 8;
            int c = wn * 32 + p * 16 + lb4 * 8;
            uint32_t t[4];
            ldsm_x4t(t, (uint32_t)__cvta_generic_to_shared(Wh + r * WPAD + c));
            bh[2*p][0] = t[0]; bh[2*p][1] = t[1]; bh[2*p+1][0] = t[2]; bh[2*p+1][1] = t[3];
            ldsm_x4t(t, (uint32_t)__cvta_generic_to_shared(Wl + r * WPAD + c));
            bl[2*p][0] = t[0]; bl[2*p][1] = t[1]; bl[2*p+1][0] = t[2]; bl[2*p+1][1] = t[3];
        }
        #pragma unroll
        for (int mt = 0; mt < 2; mt++)
            #pragma unroll
            for (int nt = 0; nt < 4; nt++) {
                mma_bf16(acc[mt][nt], ah[mt], bh[nt]);
                mma_bf16(acc[mt][nt], ah[mt], bl[nt]);
                mma_bf16(acc[mt][nt], al[mt], bh[nt]);
            }
    }

    int quad = lane >> 2;
    int tcol = (lane & 3) * 2;
    #pragma unroll
    for (int mt = 0; mt < 2; mt++) {
        int r_lo = row0 + wm * 32 + mt * 16 + quad;
        int r_hi = r_lo + 8;
        float s_lo = (r_lo < n) ? dinv[r_lo] : 0.f;
        float s_hi = (r_hi < n) ? dinv[r_hi] : 0.f;
        #pragma unroll
        for (int nt = 0; nt < 4; nt++) {
            int c = wn * 32 + nt * 8 + tcol;
            if (r_lo < n) {
                float2 v = make_float2(acc[mt][nt][0] * s_lo, acc[mt][nt][1] * s_lo);
                *(float2*)(out + (size_t)r_lo * D + c) = v;
            }
            if (r_hi < n) {
                float2 v = make_float2(acc[mt][nt][2] * s_hi, acc[mt][nt][3] * s_hi);
                *(float2*)(out + (size_t)r_hi * D + c) = v;
            }
        }
    }
}

// ---------------- fused CSR aggregate + post (LN / resid / relu / pool) ----------------
// one warp per dst row; indices prefetched lane-parallel (1 coalesced L2 access
// per 32 edges) and broadcast via shfl; gathers 8-deep in flight.
__global__ void __launch_bounds__(256)
agg_post_kernel(const float* __restrict__ g,
                const int* __restrict__ csr_src, const int* __restrict__ row_start,
                const float* __restrict__ resid,
                const float* __restrict__ dinv,
                const float* __restrict__ bias,
                const float* __restrict__ gamma,
                const float* __restrict__ beta,
                float* __restrict__ h_out,
                const int* __restrict__ batch,
                float* __restrict__ pooled,
                int n, int do_relu, int do_pool) {
    int warp = (blockIdx.x * blockDim.x + threadIdx.x) >> 5;
    int lane = threadIdx.x & 31;
    if (warp >= n) return;

    int beg = row_start[warp];
    int cnt = row_start[warp + 1] - beg;
    size_t lo = (size_t)lane * 4;

    float4 acc = *(const float4*)(g + (size_t)warp * D + lo);  // self-loop term

    for (int base = 0; base < cnt; base += 32) {
        int m = min(32, cnt - base);
        int idx = (base + lane < cnt) ? __ldg(&csr_src[beg + base + lane]) : 0;
        int j = 0;
        for (; j + 8 <= m; j += 8) {
            float4 v[8];
            #pragma unroll
            for (int k = 0; k < 8; k++) {
                int s = __shfl_sync(0xffffffffu, idx, j + k);
                v[k] = *(const float4*)(g + (size_t)s * D + lo);
            }
            #pragma unroll
            for (int k = 0; k < 8; k++) {
                acc.x += v[k].x; acc.y += v[k].y; acc.z += v[k].z; acc.w += v[k].w;
            }
        }
        for (; j + 2 <= m; j += 2) {
            int s0 = __shfl_sync(0xffffffffu, idx, j);
            int s1 = __shfl_sync(0xffffffffu, idx, j + 1);
            float4 v0 = *(const float4*)(g + (size_t)s0 * D + lo);
            float4 v1 = *(const float4*)(g + (size_t)s1 * D + lo);
            acc.x += v0.x + v1.x; acc.y += v0.y + v1.y;
            acc.z += v0.z + v1.z; acc.w += v0.w + v1.w;
        }
        if (j < m) {
            int s = __shfl_sync(0xffffffffu, idx, j);
            float4 v = *(const float4*)(g + (size_t)s * D + lo);
            acc.x += v.x; acc.y += v.y; acc.z += v.z; acc.w += v.w;
        }
    }

    float sc = dinv[warp];
    float4 b4 = *(const float4*)(bias + lo);
    float4 t;
    t.x = acc.x * sc + b4.x;
    t.y = acc.y * sc + b4.y;
    t.z = acc.z * sc + b4.z;
    t.w = acc.w * sc + b4.w;

    float sum = t.x + t.y + t.z + t.w;
    #pragma unroll
    for (int o = 16; o > 0; o >>= 1) sum += __shfl_xor_sync(0xffffffffu, sum, o);
    float mu = sum * (1.0f / D);

    float dx = t.x - mu, dy = t.y - mu, dz = t.z - mu, dw = t.w - mu;
    float ss = dx*dx + dy*dy + dz*dz + dw*dw;
    #pragma unroll
    for (int o = 16; o > 0; o >>= 1) ss += __shfl_xor_sync(0xffffffffu, ss, o);
    float inv = rsqrtf(ss * (1.0f / D) + LN_EPS);

    float4 g4 = *(const float4*)(gamma + lo);
    float4 e4 = *(const float4*)(beta + lo);

    float4 y;
    y.x = dx * inv * g4.x + e4.x;
    y.y = dy * inv * g4.y + e4.y;
    y.z = dz * inv * g4.z + e4.z;
    y.w = dw * inv * g4.w + e4.w;

    if (resid) {
        float4 r4 = *(const float4*)(resid + (size_t)warp * D + lo);
        y.x += r4.x; y.y += r4.y; y.z += r4.z; y.w += r4.w;
    }
    if (do_relu) {
        y.x = fmaxf(y.x, 0.f); y.y = fmaxf(y.y, 0.f);
        y.z = fmaxf(y.z, 0.f); y.w = fmaxf(y.w, 0.f);
    }

    if (do_pool) {
        int b = batch[warp];
        float* p = pooled + (size_t)b * D + lo;
        asm volatile("red.global.add.v4.f32 [%0], {%1,%2,%3,%4};"
                     :: "l"(p), "f"(y.x), "f"(y.y), "f"(y.z), "f"(y.w)
                     : "memory");
    } else {
        *(float4*)(h_out + (size_t)warp * D + lo) = y;
    }
}

// ---------------- final readout ----------------
__global__ void out_kernel(const float* __restrict__ pooled, const float* __restrict__ gcnt,
                           const float* __restrict__ lin_w, const float* __restrict__ lin_b,
                           float* __restrict__ out, int ngraphs) {
    int warp = (blockIdx.x * blockDim.x + threadIdx.x) >> 5;
    int lane = threadIdx.x & 31;
    if (warp >= ngraphs) return;
    float acc = 0.f;
    #pragma unroll
    for (int q = 0; q < 4; q++) {
        int j = lane + 32 * q;
        acc += pooled[(size_t)warp * D + j] * lin_w[j];
    }
    #pragma unroll
    for (int o = 16; o > 0; o >>= 1) acc += __shfl_xor_sync(0xffffffffu, acc, o);
    if (lane == 0)
        out[warp] = acc / fmaxf(gcnt[warp], 1.0f) + lin_b[0];
}

// ---------------- host launcher ----------------
extern "C" void kernel_launch(void* const* d_in, const int* in_sizes, int n_in,
                              void* d_out, int out_size) {
    const float* x      = (const float*)d_in[0];
    const void*  ei     = d_in[1];
    const void*  batch  = d_in[2];
    const float* Ws     = (const float*)d_in[3];
    const float* bs     = (const float*)d_in[4];
    const float* gammas = (const float*)d_in[5];
    const float* betas  = (const float*)d_in[6];
    const float* lin_w  = (const float*)d_in[7];
    const float* lin_b  = (const float*)d_in[8];
    float* out = (float*)d_out;

    int n = in_sizes[2];
    int E = in_sizes[1] / 2;
    int ngraphs = out_size;
    if (n > NMAX) n = NMAX;
    if (E > EMAX) E = EMAX;

    float *bufG, *bufA, *bufB, *dinv, *pooled, *gcnt;
    int *src, *dst, *csr_src, *cnt_int, *row_start, *wr_ptr, *blockSums, *batch32;
    cudaGetSymbolAddress((void**)&bufG,      d_bufG);
    cudaGetSymbolAddress((void**)&bufA,      d_bufA);
    cudaGetSymbolAddress((void**)&bufB,      d_bufB);
    cudaGetSymbolAddress((void**)&dinv,      d_dinv);
    cudaGetSymbolAddress((void**)&src,       d_src);
    cudaGetSymbolAddress((void**)&dst,       d_dst);
    cudaGetSymbolAddress((void**)&csr_src,   d_csr_src);
    cudaGetSymbolAddress((void**)&cnt_int,   d_cnt_int);
    cudaGetSymbolAddress((void**)&row_start, d_row_start);
    cudaGetSymbolAddress((void**)&wr_ptr,    d_wr_ptr);
    cudaGetSymbolAddress((void**)&blockSums, d_blockSums);
    cudaGetSymbolAddress((void**)&batch32,   d_batch32);
    cudaGetSymbolAddress((void**)&pooled,    d_pooled);
    cudaGetSymbolAddress((void**)&gcnt,      d_gcnt);

    const int smem_bytes = (2 * 128 * WPAD + 2 * 64 * WPAD) * sizeof(__nv_bfloat16);
    cudaFuncSetAttribute(gemm_kernel, cudaFuncAttributeMaxDynamicSharedMemorySize, smem_bytes);

    // ---- preamble ----
    detect_kernel<<<1, 32>>>((const int*)ei);
    cudaMemsetAsync(cnt_int, 0, (size_t)n * sizeof(int));
    cudaMemsetAsync(gcnt, 0, (size_t)ngraphs * sizeof(float));
    cudaMemsetAsync(pooled, 0, (size_t)ngraphs * D * sizeof(float));

    cvt_hist_kernel<<<(E + 255) / 256, 256>>>(ei, src, dst, cnt_int, E, n);
    cvt_batch_kernel<<<(n + 255) / 256, 256>>>(batch, batch32, gcnt, n);

    int nb = (n + SCAN_BLOCK - 1) / SCAN_BLOCK;
    scanA_kernel<<<nb, SCAN_TPB>>>(cnt_int, row_start, blockSums, n);
    scanB_kernel<<<1, SCAN_MAXBLOCKS>>>(blockSums, nb);
    scanC_kernel<<<(n + 255) / 256, 256>>>(row_start, blockSums, wr_ptr, cnt_int, dinv, n, E);
    scatter_kernel<<<(E + 255) / 256, 256>>>(src, dst, wr_ptr, csr_src, E);

    // ---- layers ----
    int gemm_blocks = (n + 63) / 64;
    int row_warp_blocks = (n + 7) / 8;
    const float* in_ptr = x;
    float* hbufs[2] = {bufA, bufB};
    for (int l = 0; l < 4; l++) {
        gemm_kernel<<<gemm_blocks, 256, smem_bytes>>>(in_ptr, Ws + (size_t)l * D * D, dinv, bufG, n);
        float* h_out = hbufs[l & 1];
        int do_pool = (l == 3);
        agg_post_kernel<<<row_warp_blocks, 256>>>(bufG, csr_src, row_start,
                                                  (l == 0) ? nullptr : in_ptr,
                                                  dinv,
                                                  bs + l * D, gammas + l * D, betas + l * D,
                                                  h_out, batch32, pooled,
                                                  n, (l < 3) ? 1 : 0, do_pool);
        in_ptr = h_out;
    }

    out_kernel<<<(ngraphs * 32 + 255) / 256, 256>>>(pooled, gcnt, lin_w, lin_b, out, ngraphs);
}

// round 6
// speedup vs baseline: 2.4664x; 1.0910x over previous
#include <cuda_runtime.h>
#include <cuda_bf16.h>
#include <stdint.h>

#define D 128
#define NMAX 100000
#define EMAX 1600000
#define NGRAPH 512
#define LN_EPS 1e-5f

#define SCAN_TPB 256
#define SCAN_ITEMS 8
#define SCAN_BLOCK (SCAN_TPB * SCAN_ITEMS)   // 2048
#define SCAN_MAXBLOCKS 1024

// ---------------- scratch (no allocs allowed) ----------------
__device__ __nv_bfloat16 d_bufG[(size_t)NMAX * D];   // g = (in @ W) * dinv[row], bf16
__device__ float d_bufA[(size_t)NMAX * D];
__device__ float d_bufB[(size_t)NMAX * D];
__device__ float d_dinv[NMAX];
__device__ int   d_src[EMAX];
__device__ int   d_dst[EMAX];
__device__ int   d_csr_src[EMAX];
__device__ int   d_cnt_int[NMAX];
__device__ int   d_row_start[NMAX + 1];
__device__ int   d_wr_ptr[NMAX];
__device__ int   d_blockSums[SCAN_MAXBLOCKS];
__device__ int   d_batch32[NMAX];
__device__ float d_pooled[NGRAPH * D];
__device__ float d_gcnt[NGRAPH];
__device__ int   d_is64;

// ---------------- dtype detection: int64 vs int32 indices ----------------
__global__ void detect_kernel(const int* __restrict__ w) {
    if (threadIdx.x == 0 && blockIdx.x == 0) {
        int zeros = 0;
        #pragma unroll
        for (int k = 0; k < 64; k++)
            if (w[2 * k + 1] == 0) zeros++;
        d_is64 = (zeros == 64) ? 1 : 0;
    }
}

// ---------------- fused: convert edges + degree histogram ----------------
__global__ void cvt_hist_kernel(const void* __restrict__ ei,
                                int* __restrict__ src, int* __restrict__ dst,
                                int* __restrict__ cnt, int E, int n) {
    int i = blockIdx.x * blockDim.x + threadIdx.x;
    if (i >= E) return;
    int s, d2;
    if (d_is64) {
        const long long* p = (const long long*)ei;
        s  = (int)p[i];
        d2 = (int)p[(size_t)E + i];
    } else {
        const int* p = (const int*)ei;
        s  = p[i];
        d2 = p[E + i];
    }
    s  = min(max(s, 0), n - 1);
    d2 = min(max(d2, 0), n - 1);
    src[i] = s;
    dst[i] = d2;
    atomicAdd(&cnt[d2], 1);
}

// ---------------- fused: convert batch + graph counts ----------------
__global__ void cvt_batch_kernel(const void* __restrict__ b,
                                 int* __restrict__ outb,
                                 float* __restrict__ gcnt, int n) {
    int i = blockIdx.x * blockDim.x + threadIdx.x;
    if (i >= n) return;
    int v;
    if (d_is64) v = (int)((const long long*)b)[i];
    else        v = ((const int*)b)[i];
    v = min(max(v, 0), NGRAPH - 1);
    outb[i] = v;
    atomicAdd(&gcnt[v], 1.0f);
}

// ---------------- exclusive scan (3 kernels) ----------------
__global__ void scanA_kernel(const int* __restrict__ cnt, int* __restrict__ row_start,
                             int* __restrict__ blockSums, int n) {
    __shared__ int ssum[SCAN_TPB];
    int b = blockIdx.x, t = threadIdx.x;
    int base = b * SCAN_BLOCK + t * SCAN_ITEMS;
    int v[SCAN_ITEMS];
    int s = 0;
    #pragma unroll
    for (int i = 0; i < SCAN_ITEMS; i++) {
        v[i] = (base + i < n) ? cnt[base + i] : 0;
        s += v[i];
    }
    ssum[t] = s;
    __syncthreads();
    for (int off = 1; off < SCAN_TPB; off <<= 1) {
        int x = (t >= off) ? ssum[t - off] : 0;
        __syncthreads();
        ssum[t] += x;
        __syncthreads();
    }
    int run = ssum[t] - s;
    #pragma unroll
    for (int i = 0; i < SCAN_ITEMS; i++) {
        if (base + i < n) row_start[base + i] = run;
        run += v[i];
    }
    if (t == SCAN_TPB - 1) blockSums[b] = ssum[t];
}

__global__ void scanB_kernel(int* __restrict__ blockSums, int nb) {
    __shared__ int ssum[SCAN_MAXBLOCKS];
    int t = threadIdx.x;
    int v = (t < nb) ? blockSums[t] : 0;
    ssum[t] = v;
    __syncthreads();
    for (int off = 1; off < SCAN_MAXBLOCKS; off <<= 1) {
        int x = (t >= off) ? ssum[t - off] : 0;
        __syncthreads();
        ssum[t] += x;
        __syncthreads();
    }
    if (t < nb) blockSums[t] = ssum[t] - v;
}

__global__ void scanC_kernel(int* __restrict__ row_start, const int* __restrict__ blockSums,
                             int* __restrict__ wr_ptr, const int* __restrict__ cnt,
                             float* __restrict__ dinv, int n, int E) {
    int i = blockIdx.x * blockDim.x + threadIdx.x;
    if (i < n) {
        int v = row_start[i] + blockSums[i / SCAN_BLOCK];
        row_start[i] = v;
        wr_ptr[i] = v;
        dinv[i] = rsqrtf((float)cnt[i] + 1.0f);
    }
    if (i == 0) row_start[n] = E;
}

__global__ void scatter_kernel(const int* __restrict__ src, const int* __restrict__ dst,
                               int* __restrict__ wr_ptr, int* __restrict__ csr_src, int E) {
    int e = blockIdx.x * blockDim.x + threadIdx.x;
    if (e < E) {
        int p = atomicAdd(&wr_ptr[dst[e]], 1);
        csr_src[p] = src[e];
    }
}

// ---------------- tensor-core GEMM: g = bf16((in @ W) * dinv[row]) ----------------
#define WPAD 136

__device__ __forceinline__ void ldsm_x4(uint32_t* r, uint32_t addr) {
    asm volatile("ldmatrix.sync.aligned.m8n8.x4.shared.b16 {%0,%1,%2,%3}, [%4];"
                 : "=r"(r[0]), "=r"(r[1]), "=r"(r[2]), "=r"(r[3]) : "r"(addr));
}
__device__ __forceinline__ void ldsm_x4t(uint32_t* r, uint32_t addr) {
    asm volatile("ldmatrix.sync.aligned.m8n8.x4.trans.shared.b16 {%0,%1,%2,%3}, [%4];"
                 : "=r"(r[0]), "=r"(r[1]), "=r"(r[2]), "=r"(r[3]) : "r"(addr));
}
__device__ __forceinline__ void mma_bf16(float* c, const uint32_t* a, const uint32_t* b) {
    asm volatile("mma.sync.aligned.m16n8k16.row.col.f32.bf16.bf16.f32 "
                 "{%0,%1,%2,%3}, {%4,%5,%6,%7}, {%8,%9}, {%0,%1,%2,%3};"
                 : "+f"(c[0]), "+f"(c[1]), "+f"(c[2]), "+f"(c[3])
                 : "r"(a[0]), "r"(a[1]), "r"(a[2]), "r"(a[3]), "r"(b[0]), "r"(b[1]));
}

__global__ void __launch_bounds__(256, 2)
gemm_kernel(const float* __restrict__ in, const float* __restrict__ W,
            const float* __restrict__ dinv, __nv_bfloat16* __restrict__ out, int n) {
    extern __shared__ __nv_bfloat16 sm[];
    __nv_bfloat16* Wh = sm;
    __nv_bfloat16* Wl = Wh + 128 * WPAD;
    __nv_bfloat16* Xh = Wl + 128 * WPAD;
    __nv_bfloat16* Xl = Xh + 64 * WPAD;

    int tid  = threadIdx.x;
    int row0 = blockIdx.x * 64;

    #pragma unroll
    for (int i = tid; i < 128 * 32; i += 256) {
        int r = i >> 5, c = (i & 31) * 4;
        float4 w = *(const float4*)(W + r * D + c);
        __nv_bfloat16 h0 = __float2bfloat16(w.x);
        __nv_bfloat16 h1 = __float2bfloat16(w.y);
        __nv_bfloat16 h2 = __float2bfloat16(w.z);
        __nv_bfloat16 h3 = __float2bfloat16(w.w);
        __nv_bfloat16* ph = Wh + r * WPAD + c;
        __nv_bfloat16* pl = Wl + r * WPAD + c;
        ph[0] = h0; ph[1] = h1; ph[2] = h2; ph[3] = h3;
        pl[0] = __float2bfloat16(w.x - __bfloat162float(h0));
        pl[1] = __float2bfloat16(w.y - __bfloat162float(h1));
        pl[2] = __float2bfloat16(w.z - __bfloat162float(h2));
        pl[3] = __float2bfloat16(w.w - __bfloat162float(h3));
    }
    #pragma unroll
    for (int i = tid; i < 64 * 32; i += 256) {
        int r = i >> 5, c = (i & 31) * 4;
        float4 v = make_float4(0.f, 0.f, 0.f, 0.f);
        if (row0 + r < n)
            v = *(const float4*)(in + (size_t)(row0 + r) * D + c);
        __nv_bfloat16 h0 = __float2bfloat16(v.x);
        __nv_bfloat16 h1 = __float2bfloat16(v.y);
        __nv_bfloat16 h2 = __float2bfloat16(v.z);
        __nv_bfloat16 h3 = __float2bfloat16(v.w);
        __nv_bfloat16* ph = Xh + r * WPAD + c;
        __nv_bfloat16* pl = Xl + r * WPAD + c;
        ph[0] = h0; ph[1] = h1; ph[2] = h2; ph[3] = h3;
        pl[0] = __float2bfloat16(v.x - __bfloat162float(h0));
        pl[1] = __float2bfloat16(v.y - __bfloat162float(h1));
        pl[2] = __float2bfloat16(v.z - __bfloat162float(h2));
        pl[3] = __float2bfloat16(v.w - __bfloat162float(h3));
    }
    __syncthreads();

    int wid  = tid >> 5;
    int lane = tid & 31;
    int wm = wid >> 2;
    int wn = wid & 3;

    int l7  = lane & 7;
    int lb3 = (lane >> 3) & 1;
    int lb4 = (lane >> 4) & 1;

    float acc[2][4][4];
    #pragma unroll
    for (int mt = 0; mt < 2; mt++)
        #pragma unroll
        for (int nt = 0; nt < 4; nt++)
            #pragma unroll
            for (int q = 0; q < 4; q++) acc[mt][nt][q] = 0.f;

    #pragma unroll
    for (int kk = 0; kk < 8; kk++) {
        int k0 = kk * 16;
        uint32_t ah[2][4], al[2][4];
        #pragma unroll
        for (int mt = 0; mt < 2; mt++) {
            int r = wm * 32 + mt * 16 + l7 + lb3 * 8;
            int c = k0 + lb4 * 8;
            ldsm_x4(ah[mt], (uint32_t)__cvta_generic_to_shared(Xh + r * WPAD + c));
            ldsm_x4(al[mt], (uint32_t)__cvta_generic_to_shared(Xl + r * WPAD + c));
        }
        uint32_t bh[4][2], bl[4][2];
        #pragma unroll
        for (int p = 0; p < 2; p++) {
            int r = k0 + l7 + lb3 * 8;
            int c = wn * 32 + p * 16 + lb4 * 8;
            uint32_t t[4];
            ldsm_x4t(t, (uint32_t)__cvta_generic_to_shared(Wh + r * WPAD + c));
            bh[2*p][0] = t[0]; bh[2*p][1] = t[1]; bh[2*p+1][0] = t[2]; bh[2*p+1][1] = t[3];
            ldsm_x4t(t, (uint32_t)__cvta_generic_to_shared(Wl + r * WPAD + c));
            bl[2*p][0] = t[0]; bl[2*p][1] = t[1]; bl[2*p+1][0] = t[2]; bl[2*p+1][1] = t[3];
        }
        #pragma unroll
        for (int mt = 0; mt < 2; mt++)
            #pragma unroll
            for (int nt = 0; nt < 4; nt++) {
                mma_bf16(acc[mt][nt], ah[mt], bh[nt]);
                mma_bf16(acc[mt][nt], ah[mt], bl[nt]);
                mma_bf16(acc[mt][nt], al[mt], bh[nt]);
            }
    }

    // epilogue: scale by dinv[row], pack bf16x2, store
    int quad = lane >> 2;
    int tcol = (lane & 3) * 2;
    #pragma unroll
    for (int mt = 0; mt < 2; mt++) {
        int r_lo = row0 + wm * 32 + mt * 16 + quad;
        int r_hi = r_lo + 8;
        float s_lo = (r_lo < n) ? dinv[r_lo] : 0.f;
        float s_hi = (r_hi < n) ? dinv[r_hi] : 0.f;
        #pragma unroll
        for (int nt = 0; nt < 4; nt++) {
            int c = wn * 32 + nt * 8 + tcol;
            if (r_lo < n) {
                __nv_bfloat162 p = __floats2bfloat162_rn(acc[mt][nt][0] * s_lo,
                                                         acc[mt][nt][1] * s_lo);
                *(uint32_t*)(out + (size_t)r_lo * D + c) = *(uint32_t*)&p;
            }
            if (r_hi < n) {
                __nv_bfloat162 p = __floats2bfloat162_rn(acc[mt][nt][2] * s_hi,
                                                         acc[mt][nt][3] * s_hi);
                *(uint32_t*)(out + (size_t)r_hi * D + c) = *(uint32_t*)&p;
            }
        }
    }
}

// ---------------- fused CSR aggregate + post ----------------
// warp per dst row, but HALF-warp per edge (2 edges in flight per warp).
// g is bf16 (256 B rows): 16 lanes x 16 B per edge.
__device__ __forceinline__ void acc_bf16x8(float* a, uint4 q) {
    __nv_bfloat162 b0 = *(__nv_bfloat162*)&q.x;
    __nv_bfloat162 b1 = *(__nv_bfloat162*)&q.y;
    __nv_bfloat162 b2 = *(__nv_bfloat162*)&q.z;
    __nv_bfloat162 b3 = *(__nv_bfloat162*)&q.w;
    float2 f0 = __bfloat1622float2(b0);
    float2 f1 = __bfloat1622float2(b1);
    float2 f2 = __bfloat1622float2(b2);
    float2 f3 = __bfloat1622float2(b3);
    a[0] += f0.x; a[1] += f0.y; a[2] += f1.x; a[3] += f1.y;
    a[4] += f2.x; a[5] += f2.y; a[6] += f3.x; a[7] += f3.y;
}

__global__ void __launch_bounds__(256)
agg_post_kernel(const __nv_bfloat16* __restrict__ g,
                const int* __restrict__ csr_src, const int* __restrict__ row_start,
                const float* __restrict__ resid,
                const float* __restrict__ dinv,
                const float* __restrict__ bias,
                const float* __restrict__ gamma,
                const float* __restrict__ beta,
                float* __restrict__ h_out,
                const int* __restrict__ batch,
                float* __restrict__ pooled,
                int n, int do_relu, int do_pool) {
    int warp = (blockIdx.x * blockDim.x + threadIdx.x) >> 5;
    int lane = threadIdx.x & 31;
    if (warp >= n) return;

    int half = lane >> 4;         // 0 or 1: which edge of the pair
    int hl   = lane & 15;         // position within half
    int colb = hl * 8;            // this lane's 8 columns

    int beg = row_start[warp];
    int cnt = row_start[warp + 1] - beg;

    float acc[8];
    #pragma unroll
    for (int k = 0; k < 8; k++) acc[k] = 0.f;

    // self-loop term: only half 0 (avoid double count after combine)
    if (half == 0) {
        uint4 q = *(const uint4*)(g + (size_t)warp * D + colb);
        acc_bf16x8(acc, q);
    }

    for (int base = 0; base < cnt; base += 32) {
        int m = min(32, cnt - base);
        int idx = (base + lane < cnt) ? __ldg(&csr_src[beg + base + lane]) : 0;
        int j = 0;
        // 4 pairs = 8 edges per iteration
        for (; j + 8 <= m; j += 8) {
            uint4 v[4];
            #pragma unroll
            for (int p = 0; p < 4; p++) {
                int s = __shfl_sync(0xffffffffu, idx, j + 2 * p + half);
                v[p] = *(const uint4*)(g + (size_t)s * D + colb);
            }
            #pragma unroll
            for (int p = 0; p < 4; p++) acc_bf16x8(acc, v[p]);
        }
        for (; j + 2 <= m; j += 2) {
            int s = __shfl_sync(0xffffffffu, idx, j + half);
            uint4 v = *(const uint4*)(g + (size_t)s * D + colb);
            acc_bf16x8(acc, v);
        }
        if (j < m) {   // odd tail: half 0 takes it
            int s = __shfl_sync(0xffffffffu, idx, j);
            if (half == 0) {
                uint4 v = *(const uint4*)(g + (size_t)s * D + colb);
                acc_bf16x8(acc, v);
            }
        }
    }

    // combine halves: lane i and i+16 hold the same columns
    #pragma unroll
    for (int k = 0; k < 8; k++)
        acc[k] += __shfl_xor_sync(0xffffffffu, acc[k], 16);

    float sc = dinv[warp];
    float t[8];
    {
        float4 b0 = *(const float4*)(bias + colb);
        float4 b1 = *(const float4*)(bias + colb + 4);
        t[0] = acc[0] * sc + b0.x; t[1] = acc[1] * sc + b0.y;
        t[2] = acc[2] * sc + b0.z; t[3] = acc[3] * sc + b0.w;
        t[4] = acc[4] * sc + b1.x; t[5] = acc[5] * sc + b1.y;
        t[6] = acc[6] * sc + b1.z; t[7] = acc[7] * sc + b1.w;
    }

    // LN: warp sums count each column twice (both halves) -> divide by 2D
    float sum = 0.f;
    #pragma unroll
    for (int k = 0; k < 8; k++) sum += t[k];
    #pragma unroll
    for (int o = 16; o > 0; o >>= 1) sum += __shfl_xor_sync(0xffffffffu, sum, o);
    float mu = sum * (1.0f / (2 * D));

    float ss = 0.f;
    #pragma unroll
    for (int k = 0; k < 8; k++) { t[k] -= mu; ss += t[k] * t[k]; }
    #pragma unroll
    for (int o = 16; o > 0; o >>= 1) ss += __shfl_xor_sync(0xffffffffu, ss, o);
    float inv = rsqrtf(ss * (1.0f / (2 * D)) + LN_EPS);

    float y[8];
    {
        float4 g0 = *(const float4*)(gamma + colb);
        float4 g1 = *(const float4*)(gamma + colb + 4);
        float4 e0 = *(const float4*)(beta + colb);
        float4 e1 = *(const float4*)(beta + colb + 4);
        y[0] = t[0] * inv * g0.x + e0.x; y[1] = t[1] * inv * g0.y + e0.y;
        y[2] = t[2] * inv * g0.z + e0.z; y[3] = t[3] * inv * g0.w + e0.w;
        y[4] = t[4] * inv * g1.x + e1.x; y[5] = t[5] * inv * g1.y + e1.y;
        y[6] = t[6] * inv * g1.z + e1.z; y[7] = t[7] * inv * g1.w + e1.w;
    }

    if (resid) {
        float4 r0 = *(const float4*)(resid + (size_t)warp * D + colb);
        float4 r1 = *(const float4*)(resid + (size_t)warp * D + colb + 4);
        y[0] += r0.x; y[1] += r0.y; y[2] += r0.z; y[3] += r0.w;
        y[4] += r1.x; y[5] += r1.y; y[6] += r1.z; y[7] += r1.w;
    }
    if (do_relu) {
        #pragma unroll
        for (int k = 0; k < 8; k++) y[k] = fmaxf(y[k], 0.f);
    }

    if (half == 0) {
        if (do_pool) {
            int b = batch[warp];
            float* p = pooled + (size_t)b * D + colb;
            asm volatile("red.global.add.v4.f32 [%0], {%1,%2,%3,%4};"
                         :: "l"(p), "f"(y[0]), "f"(y[1]), "f"(y[2]), "f"(y[3]) : "memory");
            asm volatile("red.global.add.v4.f32 [%0], {%1,%2,%3,%4};"
                         :: "l"(p + 4), "f"(y[4]), "f"(y[5]), "f"(y[6]), "f"(y[7]) : "memory");
        } else {
            float* p = h_out + (size_t)warp * D + colb;
            *(float4*)p       = make_float4(y[0], y[1], y[2], y[3]);
            *(float4*)(p + 4) = make_float4(y[4], y[5], y[6], y[7]);
        }
    }
}

// ---------------- final readout ----------------
__global__ void out_kernel(const float* __restrict__ pooled, const float* __restrict__ gcnt,
                           const float* __restrict__ lin_w, const float* __restrict__ lin_b,
                           float* __restrict__ out, int ngraphs) {
    int warp = (blockIdx.x * blockDim.x + threadIdx.x) >> 5;
    int lane = threadIdx.x & 31;
    if (warp >= ngraphs) return;
    float acc = 0.f;
    #pragma unroll
    for (int q = 0; q < 4; q++) {
        int j = lane + 32 * q;
        acc += pooled[(size_t)warp * D + j] * lin_w[j];
    }
    #pragma unroll
    for (int o = 16; o > 0; o >>= 1) acc += __shfl_xor_sync(0xffffffffu, acc, o);
    if (lane == 0)
        out[warp] = acc / fmaxf(gcnt[warp], 1.0f) + lin_b[0];
}

// ---------------- host launcher ----------------
extern "C" void kernel_launch(void* const* d_in, const int* in_sizes, int n_in,
                              void* d_out, int out_size) {
    const float* x      = (const float*)d_in[0];
    const void*  ei     = d_in[1];
    const void*  batch  = d_in[2];
    const float* Ws     = (const float*)d_in[3];
    const float* bs     = (const float*)d_in[4];
    const float* gammas = (const float*)d_in[5];
    const float* betas  = (const float*)d_in[6];
    const float* lin_w  = (const float*)d_in[7];
    const float* lin_b  = (const float*)d_in[8];
    float* out = (float*)d_out;

    int n = in_sizes[2];
    int E = in_sizes[1] / 2;
    int ngraphs = out_size;
    if (n > NMAX) n = NMAX;
    if (E > EMAX) E = EMAX;

    __nv_bfloat16* bufG;
    float *bufA, *bufB, *dinv, *pooled, *gcnt;
    int *src, *dst, *csr_src, *cnt_int, *row_start, *wr_ptr, *blockSums, *batch32;
    cudaGetSymbolAddress((void**)&bufG,      d_bufG);
    cudaGetSymbolAddress((void**)&bufA,      d_bufA);
    cudaGetSymbolAddress((void**)&bufB,      d_bufB);
    cudaGetSymbolAddress((void**)&dinv,      d_dinv);
    cudaGetSymbolAddress((void**)&src,       d_src);
    cudaGetSymbolAddress((void**)&dst,       d_dst);
    cudaGetSymbolAddress((void**)&csr_src,   d_csr_src);
    cudaGetSymbolAddress((void**)&cnt_int,   d_cnt_int);
    cudaGetSymbolAddress((void**)&row_start, d_row_start);
    cudaGetSymbolAddress((void**)&wr_ptr,    d_wr_ptr);
    cudaGetSymbolAddress((void**)&blockSums, d_blockSums);
    cudaGetSymbolAddress((void**)&batch32,   d_batch32);
    cudaGetSymbolAddress((void**)&pooled,    d_pooled);
    cudaGetSymbolAddress((void**)&gcnt,      d_gcnt);

    const int smem_bytes = (2 * 128 * WPAD + 2 * 64 * WPAD) * sizeof(__nv_bfloat16);
    cudaFuncSetAttribute(gemm_kernel, cudaFuncAttributeMaxDynamicSharedMemorySize, smem_bytes);

    // ---- preamble ----
    detect_kernel<<<1, 32>>>((const int*)ei);
    cudaMemsetAsync(cnt_int, 0, (size_t)n * sizeof(int));
    cudaMemsetAsync(gcnt, 0, (size_t)ngraphs * sizeof(float));
    cudaMemsetAsync(pooled, 0, (size_t)ngraphs * D * sizeof(float));

    cvt_hist_kernel<<<(E + 255) / 256, 256>>>(ei, src, dst, cnt_int, E, n);
    cvt_batch_kernel<<<(n + 255) / 256, 256>>>(batch, batch32, gcnt, n);

    int nb = (n + SCAN_BLOCK - 1) / SCAN_BLOCK;
    scanA_kernel<<<nb, SCAN_TPB>>>(cnt_int, row_start, blockSums, n);
    scanB_kernel<<<1, SCAN_MAXBLOCKS>>>(blockSums, nb);
    scanC_kernel<<<(n + 255) / 256, 256>>>(row_start, blockSums, wr_ptr, cnt_int, dinv, n, E);
    scatter_kernel<<<(E + 255) / 256, 256>>>(src, dst, wr_ptr, csr_src, E);

    // ---- layers ----
    int gemm_blocks = (n + 63) / 64;
    int row_warp_blocks = (n + 7) / 8;
    const float* in_ptr = x;
    float* hbufs[2] = {bufA, bufB};
    for (int l = 0; l < 4; l++) {
        gemm_kernel<<<gemm_blocks, 256, smem_bytes>>>(in_ptr, Ws + (size_t)l * D * D, dinv, bufG, n);
        float* h_out = hbufs[l & 1];
        int do_pool = (l == 3);
        agg_post_kernel<<<row_warp_blocks, 256>>>(bufG, csr_src, row_start,
                                                  (l == 0) ? nullptr : in_ptr,
                                                  dinv,
                                                  bs + l * D, gammas + l * D, betas + l * D,
                                                  h_out, batch32, pooled,
                                                  n, (l < 3) ? 1 : 0, do_pool);
        in_ptr = h_out;
    }

    out_kernel<<<(ngraphs * 32 + 255) / 256, 256>>>(pooled, gcnt, lin_w, lin_b, out, ngraphs);
}